// round 5
// baseline (speedup 1.0000x reference)
#include <cuda_runtime.h>
#include <cuda_bf16.h>
#include <cstdint>

#define NMAX 50000
#define HD 128
#define NG 128
#define NCLS 10
#define BPAD 136                      // padded row stride (bf16 elems), 272B: conflict-free ldmatrix
#define EB 128                        // edges staged per block iteration

// ---------------- scratch (device globals; no runtime allocation) -----------
__device__ float g_xA[NMAX * HD];
__device__ float g_xB[NMAX * HD];
__device__ float g_agg[NMAX * HD];
__device__ float g_h1[NMAX * HD];
__device__ float g_stats[2 * HD];   // [0:128) col sums, [128:256) col sumsq
__device__ float g_scale[HD];
__device__ float g_shift[HD];
__device__ float g_pool[NG * HD];
__device__ float g_cnt[NG];
__device__ int   g_idx64;           // 1 if indices are int64, 0 if int32
// pre-split weights in the padded SMEM image: [k][n], row stride BPAD
__device__ __nv_bfloat16 g_Whi[6][HD * BPAD];
__device__ __nv_bfloat16 g_Wlo[6][HD * BPAD];

// ---------------- helpers -----------------------------------------------------
__device__ __forceinline__ uint32_t smem_u32(const void* p) {
    uint32_t a;
    asm("{ .reg .u64 t; cvta.to.shared.u64 t, %1; cvt.u32.u64 %0, t; }"
        : "=r"(a) : "l"(p));
    return a;
}
__device__ __forceinline__ void red_add_v4(float* p, float4 v) {
    asm volatile("red.global.add.v4.f32 [%0], {%1,%2,%3,%4};"
                 :: "l"(p), "f"(v.x), "f"(v.y), "f"(v.z), "f"(v.w)
                 : "memory");
}
__device__ __forceinline__ uint32_t pack_bf(__nv_bfloat16 a, __nv_bfloat16 b) {
    uint16_t ua = *(uint16_t*)&a, ub = *(uint16_t*)&b;
    return (uint32_t)ua | ((uint32_t)ub << 16);
}
__device__ __forceinline__ void ldmatrix_x4(uint32_t* r, uint32_t addr) {
    asm volatile("ldmatrix.sync.aligned.m8n8.x4.shared.b16 {%0,%1,%2,%3}, [%4];"
                 : "=r"(r[0]), "=r"(r[1]), "=r"(r[2]), "=r"(r[3]) : "r"(addr));
}
__device__ __forceinline__ void ldmatrix_x4_trans(uint32_t* r, uint32_t addr) {
    asm volatile("ldmatrix.sync.aligned.m8n8.x4.trans.shared.b16 {%0,%1,%2,%3}, [%4];"
                 : "=r"(r[0]), "=r"(r[1]), "=r"(r[2]), "=r"(r[3]) : "r"(addr));
}
__device__ __forceinline__ void mma_bf16(float* c, const uint32_t* a, const uint32_t* b) {
    asm volatile(
        "mma.sync.aligned.m16n8k16.row.col.f32.bf16.bf16.f32 "
        "{%0,%1,%2,%3}, {%4,%5,%6,%7}, {%8,%9}, {%0,%1,%2,%3};"
        : "+f"(c[0]), "+f"(c[1]), "+f"(c[2]), "+f"(c[3])
        : "r"(a[0]), "r"(a[1]), "r"(a[2]), "r"(a[3]), "r"(b[0]), "r"(b[1]));
}

// ---------------- index dtype detect ------------------------------------------
__global__ void detect_idx_kernel(const void* ei, int E, int n) {
    if (threadIdx.x != 0 || blockIdx.x != 0) return;
    const long long* p64 = (const long long*)ei;
    int ok64 = 1;
    for (int i = 0; i < 16; i++) {
        long long v = p64[i];
        if (v < 0 || v >= (long long)n) { ok64 = 0; break; }
    }
    if (ok64) {
        for (int i = 0; i < 16; i++) {
            long long v = p64[(size_t)E + i];
            if (v < 0 || v >= (long long)n) { ok64 = 0; break; }
        }
    }
    g_idx64 = ok64;
}
__device__ __forceinline__ long long load_index(const void* base, long long off, int is64) {
    if (is64) return ((const long long*)base)[off];
    return (long long)((const int*)base)[off];
}

// ---------------- small utility kernels --------------------------------------
__global__ void zero_agg_stats_kernel(int n4) {
    int i = blockIdx.x * blockDim.x + threadIdx.x;
    if (i < 2 * HD) g_stats[i] = 0.f;
    float4 z = make_float4(0.f, 0.f, 0.f, 0.f);
    float4* a = reinterpret_cast<float4*>(g_agg);
    for (int j = i; j < n4; j += gridDim.x * blockDim.x) a[j] = z;
}
__global__ void zero_pool_kernel() {
    int i = blockIdx.x * blockDim.x + threadIdx.x;
    if (i < NG * HD) g_pool[i] = 0.f;
    if (i < NG) g_cnt[i] = 0.f;
}

// ---------------- weight pre-split (all 6 slots in one launch) -----------------
__global__ void conv_w_all_kernel(const float* __restrict__ W1,
                                  const float* __restrict__ W2) {
    int i = blockIdx.x * blockDim.x + threadIdx.x;
    if (i >= 6 * HD * HD) return;
    int slot = i >> 14;
    int j = i & (HD * HD - 1);
    int n = j & 127, k = j >> 7;
    const float* W = (slot < 3) ? (W1 + (size_t)slot * HD * HD)
                                : (W2 + (size_t)(slot - 3) * HD * HD);
    float w = W[k * HD + n];
    __nv_bfloat16 hi = __float2bfloat16(w);
    float lof = w - __bfloat162float(hi);
    g_Whi[slot][k * BPAD + n] = hi;
    g_Wlo[slot][k * BPAD + n] = __float2bfloat16(lof);
}

// ---------------- edge aggregation: agg[dst] += x[src] * ec ------------------
// Block stages EB edges' indices in SMEM; 8 warps each handle EB/8 edges with a
// 2-deep gather/RED software pipeline for MLP.
__global__ __launch_bounds__(256, 4)
void edge_agg_kernel(const void* __restrict__ ei,
                     const float* __restrict__ ec,
                     int E, const float* __restrict__ x) {
    __shared__ int s_src[EB];
    __shared__ int s_dst[EB];
    __shared__ float s_w[EB];
    int tid = threadIdx.x, wid = tid >> 5, lane = tid & 31;
    int is64 = g_idx64;

    long long base = (long long)blockIdx.x * EB;
    if (base >= E) return;
    int cnt = min(EB, (int)(E - base));
    if (tid < cnt) {
        s_src[tid] = (int)load_index(ei, base + tid, is64);
        s_dst[tid] = (int)load_index(ei, (long long)E + base + tid, is64);
        s_w[tid] = __ldg(ec + base + tid);
    }
    __syncthreads();

    int e = wid;
    if (e < cnt) {
        int s = s_src[e];
        float4 v = *reinterpret_cast<const float4*>(x + (size_t)s * HD + lane * 4);
        while (true) {
            int en = e + 8;
            float4 vn;
            if (en < cnt) {
                int sn = s_src[en];
                vn = *reinterpret_cast<const float4*>(x + (size_t)sn * HD + lane * 4);
            }
            float w = s_w[e];
            int d = s_dst[e];
            float4 o = make_float4(v.x * w, v.y * w, v.z * w, v.w * w);
            red_add_v4(g_agg + (size_t)d * HD + lane * 4, o);
            if (en >= cnt) break;
            v = vn; e = en;
        }
    }
}

// ---------------- tensor-core bf16x3 fused GEMM (one tile per CTA) -------------
// MODE 0: A = x_in + agg * nc[row];  C = h1 = A @ W1 + b1; accumulate col stats
// MODE 1: A = relu(h1 * scale[k] + shift[k]); C = x_out = relu(A @ W2 + b2)
#define TILE_BYTES (HD * BPAD * 2)          // 34816
#define S_AHI 0
#define S_ALO TILE_BYTES
#define S_BHI (2 * TILE_BYTES)
#define S_BLO (3 * TILE_BYTES)
#define SMEM_SZ (4 * TILE_BYTES)            // 139264

template <int MODE>
__global__ __launch_bounds__(256, 1)
void tgemm_kernel(const float* __restrict__ Ain,
                  float* __restrict__ Cout,
                  const float* __restrict__ nc,
                  const float* __restrict__ bias,
                  int n, int slot) {
    extern __shared__ char smem[];
    uint32_t sb = smem_u32(smem);
    int tid = threadIdx.x, wid = tid >> 5, lane = tid & 31;
    int block_row = blockIdx.x * 128;
    int warp_m = wid & 3;                    // rows warp_m*32
    int warp_n = wid >> 2;                   // cols warp_n*64

    // ---- copy pre-split W tiles (already padded image) ----
    {
        const uint4* wh = (const uint4*)g_Whi[slot];
        const uint4* wl = (const uint4*)g_Wlo[slot];
        uint4* dh = (uint4*)(smem + S_BHI);
        uint4* dl = (uint4*)(smem + S_BLO);
        for (int i = tid; i < TILE_BYTES / 16; i += 256) {
            dh[i] = wh[i];
            dl[i] = wl[i];
        }
    }

    // ---- fused A producer: load, fuse, bf16 hi/lo split ----
#pragma unroll 4
    for (int it = 0; it < 16; it++) {
        int f = tid + it * 256;              // 0..4095 float4 slots
        int row = f >> 5;                    // 0..127
        int kk = (f & 31) << 2;              // 0..124
        int grow = block_row + row;
        float4 v = make_float4(0.f, 0.f, 0.f, 0.f);
        if (grow < n) {
            v = *reinterpret_cast<const float4*>(Ain + (size_t)grow * HD + kk);
            if (MODE == 0) {
                float w = __ldg(nc + grow);
                float4 u = *reinterpret_cast<const float4*>(g_agg + (size_t)grow * HD + kk);
                v.x = fmaf(u.x, w, v.x);
                v.y = fmaf(u.y, w, v.y);
                v.z = fmaf(u.z, w, v.z);
                v.w = fmaf(u.w, w, v.w);
            } else {
                float4 sc = *reinterpret_cast<const float4*>(g_scale + kk);
                float4 sh = *reinterpret_cast<const float4*>(g_shift + kk);
                v.x = fmaxf(fmaf(v.x, sc.x, sh.x), 0.f);
                v.y = fmaxf(fmaf(v.y, sc.y, sh.y), 0.f);
                v.z = fmaxf(fmaf(v.z, sc.z, sh.z), 0.f);
                v.w = fmaxf(fmaf(v.w, sc.w, sh.w), 0.f);
            }
        }
        __nv_bfloat16 h0 = __float2bfloat16(v.x);
        __nv_bfloat16 h1 = __float2bfloat16(v.y);
        __nv_bfloat16 h2 = __float2bfloat16(v.z);
        __nv_bfloat16 h3 = __float2bfloat16(v.w);
        __nv_bfloat16 l0 = __float2bfloat16(v.x - __bfloat162float(h0));
        __nv_bfloat16 l1 = __float2bfloat16(v.y - __bfloat162float(h1));
        __nv_bfloat16 l2 = __float2bfloat16(v.z - __bfloat162float(h2));
        __nv_bfloat16 l3 = __float2bfloat16(v.w - __bfloat162float(h3));
        uint2 hp; hp.x = pack_bf(h0, h1); hp.y = pack_bf(h2, h3);
        uint2 lp; lp.x = pack_bf(l0, l1); lp.y = pack_bf(l2, l3);
        int off = row * (BPAD * 2) + kk * 2;     // bytes
        *(uint2*)(smem + S_AHI + off) = hp;
        *(uint2*)(smem + S_ALO + off) = lp;
    }
    __syncthreads();

    // ---- MMA mainloop: 8 k-steps, 3 products, fp32 accumulate ----
    float acc[2][8][4];
#pragma unroll
    for (int mf = 0; mf < 2; mf++)
#pragma unroll
        for (int nf = 0; nf < 8; nf++)
#pragma unroll
            for (int q = 0; q < 4; q++) acc[mf][nf][q] = 0.f;

    // per-lane ldmatrix base offsets
    int lrow = lane & 15;                    // matrix row
    int lblk = (lane >> 4) * 16;             // +16B for second 8-col block
    uint32_t aBase = sb + (warp_m * 32 + lrow) * (BPAD * 2) + lblk;
    uint32_t bBase = sb + lrow * (BPAD * 2) + (warp_n * 64) * 2 + lblk;

#pragma unroll
    for (int ks = 0; ks < 8; ks++) {
        uint32_t ah[2][4], al[2][4], bh[8][2], bl[8][2];
#pragma unroll
        for (int mf = 0; mf < 2; mf++) {
            uint32_t addr = aBase + mf * 16 * (BPAD * 2) + ks * 32;
            ldmatrix_x4(ah[mf], addr + S_AHI);
            ldmatrix_x4(al[mf], addr + S_ALO);
        }
#pragma unroll
        for (int nb = 0; nb < 4; nb++) {
            uint32_t addr = bBase + ks * 16 * (BPAD * 2) + nb * 32;
            uint32_t rh[4], rl[4];
            ldmatrix_x4_trans(rh, addr + S_BHI);
            ldmatrix_x4_trans(rl, addr + S_BLO);
            bh[2 * nb][0] = rh[0]; bh[2 * nb][1] = rh[1];
            bh[2 * nb + 1][0] = rh[2]; bh[2 * nb + 1][1] = rh[3];
            bl[2 * nb][0] = rl[0]; bl[2 * nb][1] = rl[1];
            bl[2 * nb + 1][0] = rl[2]; bl[2 * nb + 1][1] = rl[3];
        }
#pragma unroll
        for (int mf = 0; mf < 2; mf++)
#pragma unroll
            for (int nf = 0; nf < 8; nf++) {
                mma_bf16(acc[mf][nf], ah[mf], bh[nf]);
                mma_bf16(acc[mf][nf], ah[mf], bl[nf]);
                mma_bf16(acc[mf][nf], al[mf], bh[nf]);
            }
    }

    // ---- epilogue: bias, (stats | relu), direct fragment stores ----
    int r0 = block_row + warp_m * 32 + (lane >> 2);   // rows r0, r0+8, r0+16, r0+24
#pragma unroll
    for (int nf = 0; nf < 8; nf++) {
        int col = warp_n * 64 + nf * 8 + (lane & 3) * 2;
        float b0 = __ldg(bias + col), b1 = __ldg(bias + col + 1);
        float v[4][2];
#pragma unroll
        for (int mf = 0; mf < 2; mf++) {
            v[mf * 2][0] = acc[mf][nf][0] + b0;
            v[mf * 2][1] = acc[mf][nf][1] + b1;
            v[mf * 2 + 1][0] = acc[mf][nf][2] + b0;
            v[mf * 2 + 1][1] = acc[mf][nf][3] + b1;
        }
        bool val[4];
        val[0] = r0 < n; val[1] = r0 + 8 < n; val[2] = r0 + 16 < n; val[3] = r0 + 24 < n;
        if (MODE == 0) {
            float s0 = 0.f, s1 = 0.f, q0 = 0.f, q1 = 0.f;
#pragma unroll
            for (int p = 0; p < 4; p++) {
                if (val[p]) {
                    s0 += v[p][0]; q0 += v[p][0] * v[p][0];
                    s1 += v[p][1]; q1 += v[p][1] * v[p][1];
                }
            }
#pragma unroll
            for (int d = 4; d < 32; d <<= 1) {
                s0 += __shfl_xor_sync(0xFFFFFFFFu, s0, d);
                s1 += __shfl_xor_sync(0xFFFFFFFFu, s1, d);
                q0 += __shfl_xor_sync(0xFFFFFFFFu, q0, d);
                q1 += __shfl_xor_sync(0xFFFFFFFFu, q1, d);
            }
            if (lane < 4) {
                int c0 = warp_n * 64 + nf * 8 + lane * 2;
                atomicAdd(&g_stats[c0], s0);
                atomicAdd(&g_stats[c0 + 1], s1);
                atomicAdd(&g_stats[HD + c0], q0);
                atomicAdd(&g_stats[HD + c0 + 1], q1);
            }
        } else {
#pragma unroll
            for (int p = 0; p < 4; p++) {
                v[p][0] = fmaxf(v[p][0], 0.f);
                v[p][1] = fmaxf(v[p][1], 0.f);
            }
        }
        // stores: rows r0 + {0,8,16,24}
#pragma unroll
        for (int p = 0; p < 4; p++) {
            int row = r0 + ((p & 1) ? 8 : 0) + ((p >> 1) ? 16 : 0);
            int pi = (p & 1) + (p >> 1) * 2;   // map store order to v index
            if (row < n) {
                float2 o = make_float2(v[pi][0], v[pi][1]);
                *reinterpret_cast<float2*>(Cout + (size_t)row * HD + col) = o;
            }
        }
    }
}

// ---------------- BN parameter computation ------------------------------------
__global__ void bn_params_kernel(const float* __restrict__ gamma,
                                 const float* __restrict__ beta, int n) {
    int h = threadIdx.x;
    float invn = 1.f / (float)n;
    float mu = g_stats[h] * invn;
    float var = g_stats[HD + h] * invn - mu * mu;
    float s = gamma[h] * rsqrtf(var + 1e-5f);
    g_scale[h] = s;
    g_shift[h] = beta[h] - mu * s;
}

// ---------------- pooling ------------------------------------------------------
__global__ void pool_kernel(const void* __restrict__ batch, int n,
                            const float* __restrict__ x) {
    int i = blockIdx.x * (blockDim.x >> 5) + (threadIdx.x >> 5);
    if (i >= n) return;
    int lane = threadIdx.x & 31;
    int is64 = g_idx64;
    long long g = load_index(batch, i, is64);
    float4 v = *reinterpret_cast<const float4*>(x + (size_t)i * HD + lane * 4);
    red_add_v4(g_pool + g * HD + lane * 4, v);
    if (lane == 0) atomicAdd(&g_cnt[g], 1.f);
}

// ---------------- classifier head ----------------------------------------------
__global__ void head_kernel(const float* __restrict__ Wc,
                            const float* __restrict__ bc,
                            float* __restrict__ out) {
    int g = blockIdx.x;
    int h = threadIdx.x;
    float cnt = g_cnt[g];
    float v = g_pool[g * HD + h] / fmaxf(cnt, 1.f);
    __shared__ float sh[HD];
    for (int c = 0; c < NCLS; c++) {
        sh[h] = v * Wc[h * NCLS + c];
        __syncthreads();
        for (int s = 64; s > 0; s >>= 1) {
            if (h < s) sh[h] += sh[h + s];
            __syncthreads();
        }
        if (h == 0) out[g * NCLS + c] = sh[0] + bc[c];
        __syncthreads();
    }
}

// ---------------- launch ---------------------------------------------------------
extern "C" void kernel_launch(void* const* d_in, const int* in_sizes, int n_in,
                              void* d_out, int out_size) {
    cudaFuncSetAttribute(tgemm_kernel<0>,
                         cudaFuncAttributeMaxDynamicSharedMemorySize, SMEM_SZ);
    cudaFuncSetAttribute(tgemm_kernel<1>,
                         cudaFuncAttributeMaxDynamicSharedMemorySize, SMEM_SZ);

    // Detect input ordering: signature order has edge_index (1.6M elems) at [1];
    // setup_inputs dict order has node_centrality (50K) at [1].
    int ix, iei, ib, inc_, iec, iw1, ib1, ig1, ibe1, iw2, ib2, iwc, ibc;
    ix = 0;
    if (n_in >= 13 && in_sizes[1] > 1000000) {
        iei = 1; ib = 2; inc_ = 3; iec = 4;
        iw1 = 5; ib1 = 6; ig1 = 7; ibe1 = 8;
        iw2 = 9; ib2 = 10; iwc = 11; ibc = 12;
    } else {
        inc_ = 1; iec = 2; iw1 = 3; ib1 = 4; ig1 = 5; ibe1 = 6;
        iw2 = 7; ib2 = 8; iwc = 9; ibc = 10; iei = 11; ib = 12;
    }

    const float* x   = (const float*)d_in[ix];
    const void*  ei  = d_in[iei];
    const void*  bat = d_in[ib];
    const float* nc  = (const float*)d_in[inc_];
    const float* ec  = (const float*)d_in[iec];
    const float* W1  = (const float*)d_in[iw1];
    const float* b1  = (const float*)d_in[ib1];
    const float* g1  = (const float*)d_in[ig1];
    const float* be1 = (const float*)d_in[ibe1];
    const float* W2  = (const float*)d_in[iw2];
    const float* b2  = (const float*)d_in[ib2];
    const float* Wc  = (const float*)d_in[iwc];
    const float* bc  = (const float*)d_in[ibc];
    float* out = (float*)d_out;

    int n = in_sizes[ix] / HD;
    int E = in_sizes[iei] / 2;
    int n4 = n * (HD / 4);

    detect_idx_kernel<<<1, 32>>>(ei, E, n);
    conv_w_all_kernel<<<(6 * HD * HD + 255) / 256, 256>>>(W1, W2);

    int gemm_blocks = (n + 127) / 128;
    int edge_blocks = (E + EB - 1) / EB;
    int pool_blocks = (n + 7) / 8;

    // layer I/O ping-pong: in x -> B -> A -> B (no initial copy)
    const float* lin[3] = { x, g_xB, g_xA };
    float* lout[3] = { g_xB, g_xA, g_xB };

    for (int l = 0; l < 3; l++) {
        zero_agg_stats_kernel<<<2048, 256>>>(n4);
        edge_agg_kernel<<<edge_blocks, 256>>>(ei, ec, E, lin[l]);
        tgemm_kernel<0><<<gemm_blocks, 256, SMEM_SZ>>>(lin[l], g_h1, nc,
                                                       b1 + l * HD, n, l);
        bn_params_kernel<<<1, HD>>>(g1 + l * HD, be1 + l * HD, n);
        tgemm_kernel<1><<<gemm_blocks, 256, SMEM_SZ>>>(g_h1, lout[l], nullptr,
                                                       b2 + l * HD, n, 3 + l);
    }

    zero_pool_kernel<<<64, 256>>>();
    pool_kernel<<<pool_blocks, 256>>>(bat, n, g_xB);
    head_kernel<<<NG, HD>>>(Wc, bc, out);
}

// round 6
// speedup vs baseline: 11.0228x; 11.0228x over previous
#include <cuda_runtime.h>
#include <cuda_bf16.h>
#include <cstdint>

#define NMAX 50000
#define HD 128
#define NG 128
#define NCLS 10
#define BPAD 136                      // padded row stride (bf16 elems), 272B: conflict-free ldmatrix
#define EB 128                        // edges staged per block iteration

// ---------------- scratch (device globals; no runtime allocation) -----------
// NOTE: these are referenced ONLY from device code (selected via int selectors).
// Passing their addresses from host code caused the round-4/5 5.9ms regression.
__device__ float g_xA[NMAX * HD];
__device__ float g_xB[NMAX * HD];
__device__ float g_agg[NMAX * HD];
__device__ float g_h1[NMAX * HD];
__device__ float g_stats[2 * HD];   // [0:128) col sums, [128:256) col sumsq
__device__ float g_scale[HD];
__device__ float g_shift[HD];
__device__ float g_pool[NG * HD];
__device__ float g_cnt[NG];
__device__ int   g_idx64;           // 1 if indices are int64, 0 if int32
// pre-split weights in the padded SMEM image: [k][n], row stride BPAD
__device__ __nv_bfloat16 g_Whi[6][HD * BPAD];
__device__ __nv_bfloat16 g_Wlo[6][HD * BPAD];

// ---------------- helpers -----------------------------------------------------
__device__ __forceinline__ uint32_t smem_u32(const void* p) {
    uint32_t a;
    asm("{ .reg .u64 t; cvta.to.shared.u64 t, %1; cvt.u32.u64 %0, t; }"
        : "=r"(a) : "l"(p));
    return a;
}
__device__ __forceinline__ void red_add_v4(float* p, float4 v) {
    asm volatile("red.global.add.v4.f32 [%0], {%1,%2,%3,%4};"
                 :: "l"(p), "f"(v.x), "f"(v.y), "f"(v.z), "f"(v.w)
                 : "memory");
}
__device__ __forceinline__ uint32_t pack_bf(__nv_bfloat16 a, __nv_bfloat16 b) {
    uint16_t ua = *(uint16_t*)&a, ub = *(uint16_t*)&b;
    return (uint32_t)ua | ((uint32_t)ub << 16);
}
__device__ __forceinline__ void ldmatrix_x4(uint32_t* r, uint32_t addr) {
    asm volatile("ldmatrix.sync.aligned.m8n8.x4.shared.b16 {%0,%1,%2,%3}, [%4];"
                 : "=r"(r[0]), "=r"(r[1]), "=r"(r[2]), "=r"(r[3]) : "r"(addr));
}
__device__ __forceinline__ void ldmatrix_x4_trans(uint32_t* r, uint32_t addr) {
    asm volatile("ldmatrix.sync.aligned.m8n8.x4.trans.shared.b16 {%0,%1,%2,%3}, [%4];"
                 : "=r"(r[0]), "=r"(r[1]), "=r"(r[2]), "=r"(r[3]) : "r"(addr));
}
__device__ __forceinline__ void mma_bf16(float* c, const uint32_t* a, const uint32_t* b) {
    asm volatile(
        "mma.sync.aligned.m16n8k16.row.col.f32.bf16.bf16.f32 "
        "{%0,%1,%2,%3}, {%4,%5,%6,%7}, {%8,%9}, {%0,%1,%2,%3};"
        : "+f"(c[0]), "+f"(c[1]), "+f"(c[2]), "+f"(c[3])
        : "r"(a[0]), "r"(a[1]), "r"(a[2]), "r"(a[3]), "r"(b[0]), "r"(b[1]));
}

// ---------------- index dtype detect ------------------------------------------
__global__ void detect_idx_kernel(const void* ei, int E, int n) {
    if (threadIdx.x != 0 || blockIdx.x != 0) return;
    const long long* p64 = (const long long*)ei;
    int ok64 = 1;
    for (int i = 0; i < 16; i++) {
        long long v = p64[i];
        if (v < 0 || v >= (long long)n) { ok64 = 0; break; }
    }
    if (ok64) {
        for (int i = 0; i < 16; i++) {
            long long v = p64[(size_t)E + i];
            if (v < 0 || v >= (long long)n) { ok64 = 0; break; }
        }
    }
    g_idx64 = ok64;
}
__device__ __forceinline__ long long load_index(const void* base, long long off, int is64) {
    if (is64) return ((const long long*)base)[off];
    return (long long)((const int*)base)[off];
}

// ---------------- small utility kernels --------------------------------------
__global__ void copy_x_kernel(const float4* __restrict__ src, int n4) {
    float4* dst = reinterpret_cast<float4*>(g_xA);
    for (int i = blockIdx.x * blockDim.x + threadIdx.x; i < n4;
         i += gridDim.x * blockDim.x)
        dst[i] = src[i];
}
__global__ void zero_agg_stats_kernel(int n4) {
    int i = blockIdx.x * blockDim.x + threadIdx.x;
    if (i < 2 * HD) g_stats[i] = 0.f;
    float4 z = make_float4(0.f, 0.f, 0.f, 0.f);
    float4* a = reinterpret_cast<float4*>(g_agg);
    for (int j = i; j < n4; j += gridDim.x * blockDim.x) a[j] = z;
}
__global__ void zero_pool_kernel() {
    int i = blockIdx.x * blockDim.x + threadIdx.x;
    if (i < NG * HD) g_pool[i] = 0.f;
    if (i < NG) g_cnt[i] = 0.f;
}

// ---------------- weight pre-split (all 6 slots in one launch) -----------------
__global__ void conv_w_all_kernel(const float* __restrict__ W1,
                                  const float* __restrict__ W2) {
    int i = blockIdx.x * blockDim.x + threadIdx.x;
    if (i >= 6 * HD * HD) return;
    int slot = i >> 14;
    int j = i & (HD * HD - 1);
    int n = j & 127, k = j >> 7;
    const float* W = (slot < 3) ? (W1 + (size_t)slot * HD * HD)
                                : (W2 + (size_t)(slot - 3) * HD * HD);
    float w = W[k * HD + n];
    __nv_bfloat16 hi = __float2bfloat16(w);
    float lof = w - __bfloat162float(hi);
    g_Whi[slot][k * BPAD + n] = hi;
    g_Wlo[slot][k * BPAD + n] = __float2bfloat16(lof);
}

// ---------------- edge aggregation: agg[dst] += x[src] * ec ------------------
// Block stages EB edges' indices in SMEM; 8 warps each handle EB/8 edges with a
// 2-deep gather/RED software pipeline for MLP. x selected device-side via sel.
__global__ __launch_bounds__(256, 4)
void edge_agg_kernel(const void* __restrict__ ei,
                     const float* __restrict__ ec,
                     int E, int sel) {
    __shared__ int s_src[EB];
    __shared__ int s_dst[EB];
    __shared__ float s_w[EB];
    int tid = threadIdx.x, wid = tid >> 5, lane = tid & 31;
    int is64 = g_idx64;
    const float* x = sel ? g_xB : g_xA;

    long long base = (long long)blockIdx.x * EB;
    if (base >= E) return;
    int cnt = min(EB, (int)(E - base));
    if (tid < cnt) {
        s_src[tid] = (int)load_index(ei, base + tid, is64);
        s_dst[tid] = (int)load_index(ei, (long long)E + base + tid, is64);
        s_w[tid] = __ldg(ec + base + tid);
    }
    __syncthreads();

    int e = wid;
    if (e < cnt) {
        int s = s_src[e];
        float4 v = *reinterpret_cast<const float4*>(x + (size_t)s * HD + lane * 4);
        while (true) {
            int en = e + 8;
            float4 vn;
            if (en < cnt) {
                int sn = s_src[en];
                vn = *reinterpret_cast<const float4*>(x + (size_t)sn * HD + lane * 4);
            }
            float w = s_w[e];
            int d = s_dst[e];
            float4 o = make_float4(v.x * w, v.y * w, v.z * w, v.w * w);
            red_add_v4(g_agg + (size_t)d * HD + lane * 4, o);
            if (en >= cnt) break;
            v = vn; e = en;
        }
    }
}

// ---------------- tensor-core bf16x3 fused GEMM (one tile per CTA) -------------
// MODE 0: A = x_in + agg * nc[row];  C = h1 = A @ W1 + b1; accumulate col stats
// MODE 1: A = relu(h1 * scale[k] + shift[k]); C = x_out = relu(A @ W2 + b2)
// Buffers selected INSIDE the kernel from the sel int (never host-passed).
#define TILE_BYTES (HD * BPAD * 2)          // 34816
#define S_AHI 0
#define S_ALO TILE_BYTES
#define S_BHI (2 * TILE_BYTES)
#define S_BLO (3 * TILE_BYTES)
#define SMEM_SZ (4 * TILE_BYTES)            // 139264

template <int MODE>
__global__ __launch_bounds__(256, 1)
void tgemm_kernel(const float* __restrict__ nc,
                  const float* __restrict__ bias,
                  int n, int sel, int slot) {
    extern __shared__ char smem[];
    uint32_t sb = smem_u32(smem);
    int tid = threadIdx.x, wid = tid >> 5, lane = tid & 31;
    int block_row = blockIdx.x * 128;
    int warp_m = wid & 3;                    // rows warp_m*32
    int warp_n = wid >> 2;                   // cols warp_n*64

    const float* Ain;
    float* Cout;
    if (MODE == 0) { Ain = sel ? g_xB : g_xA; Cout = g_h1; }
    else           { Ain = g_h1;              Cout = sel ? g_xB : g_xA; }

    // ---- copy pre-split W tiles (already padded image) ----
    {
        const uint4* wh = (const uint4*)g_Whi[slot];
        const uint4* wl = (const uint4*)g_Wlo[slot];
        uint4* dh = (uint4*)(smem + S_BHI);
        uint4* dl = (uint4*)(smem + S_BLO);
        for (int i = tid; i < TILE_BYTES / 16; i += 256) {
            dh[i] = wh[i];
            dl[i] = wl[i];
        }
    }

    // ---- fused A producer: load, fuse, bf16 hi/lo split ----
#pragma unroll 4
    for (int it = 0; it < 16; it++) {
        int f = tid + it * 256;              // 0..4095 float4 slots
        int row = f >> 5;                    // 0..127
        int kk = (f & 31) << 2;              // 0..124
        int grow = block_row + row;
        float4 v = make_float4(0.f, 0.f, 0.f, 0.f);
        if (grow < n) {
            v = *reinterpret_cast<const float4*>(Ain + (size_t)grow * HD + kk);
            if (MODE == 0) {
                float w = __ldg(nc + grow);
                float4 u = *reinterpret_cast<const float4*>(g_agg + (size_t)grow * HD + kk);
                v.x = fmaf(u.x, w, v.x);
                v.y = fmaf(u.y, w, v.y);
                v.z = fmaf(u.z, w, v.z);
                v.w = fmaf(u.w, w, v.w);
            } else {
                float4 sc = *reinterpret_cast<const float4*>(g_scale + kk);
                float4 sh = *reinterpret_cast<const float4*>(g_shift + kk);
                v.x = fmaxf(fmaf(v.x, sc.x, sh.x), 0.f);
                v.y = fmaxf(fmaf(v.y, sc.y, sh.y), 0.f);
                v.z = fmaxf(fmaf(v.z, sc.z, sh.z), 0.f);
                v.w = fmaxf(fmaf(v.w, sc.w, sh.w), 0.f);
            }
        }
        __nv_bfloat16 h0 = __float2bfloat16(v.x);
        __nv_bfloat16 h1 = __float2bfloat16(v.y);
        __nv_bfloat16 h2 = __float2bfloat16(v.z);
        __nv_bfloat16 h3 = __float2bfloat16(v.w);
        __nv_bfloat16 l0 = __float2bfloat16(v.x - __bfloat162float(h0));
        __nv_bfloat16 l1 = __float2bfloat16(v.y - __bfloat162float(h1));
        __nv_bfloat16 l2 = __float2bfloat16(v.z - __bfloat162float(h2));
        __nv_bfloat16 l3 = __float2bfloat16(v.w - __bfloat162float(h3));
        uint2 hp; hp.x = pack_bf(h0, h1); hp.y = pack_bf(h2, h3);
        uint2 lp; lp.x = pack_bf(l0, l1); lp.y = pack_bf(l2, l3);
        int off = row * (BPAD * 2) + kk * 2;     // bytes
        *(uint2*)(smem + S_AHI + off) = hp;
        *(uint2*)(smem + S_ALO + off) = lp;
    }
    __syncthreads();

    // ---- MMA mainloop: 8 k-steps, 3 products, fp32 accumulate ----
    float acc[2][8][4];
#pragma unroll
    for (int mf = 0; mf < 2; mf++)
#pragma unroll
        for (int nf = 0; nf < 8; nf++)
#pragma unroll
            for (int q = 0; q < 4; q++) acc[mf][nf][q] = 0.f;

    // per-lane ldmatrix base offsets
    int lrow = lane & 15;                    // matrix row
    int lblk = (lane >> 4) * 16;             // +16B for second 8-col block
    uint32_t aBase = sb + (warp_m * 32 + lrow) * (BPAD * 2) + lblk;
    uint32_t bBase = sb + lrow * (BPAD * 2) + (warp_n * 64) * 2 + lblk;

#pragma unroll
    for (int ks = 0; ks < 8; ks++) {
        uint32_t ah[2][4], al[2][4], bh[8][2], bl[8][2];
#pragma unroll
        for (int mf = 0; mf < 2; mf++) {
            uint32_t addr = aBase + mf * 16 * (BPAD * 2) + ks * 32;
            ldmatrix_x4(ah[mf], addr + S_AHI);
            ldmatrix_x4(al[mf], addr + S_ALO);
        }
#pragma unroll
        for (int nb = 0; nb < 4; nb++) {
            uint32_t addr = bBase + ks * 16 * (BPAD * 2) + nb * 32;
            uint32_t rh[4], rl[4];
            ldmatrix_x4_trans(rh, addr + S_BHI);
            ldmatrix_x4_trans(rl, addr + S_BLO);
            bh[2 * nb][0] = rh[0]; bh[2 * nb][1] = rh[1];
            bh[2 * nb + 1][0] = rh[2]; bh[2 * nb + 1][1] = rh[3];
            bl[2 * nb][0] = rl[0]; bl[2 * nb][1] = rl[1];
            bl[2 * nb + 1][0] = rl[2]; bl[2 * nb + 1][1] = rl[3];
        }
#pragma unroll
        for (int mf = 0; mf < 2; mf++)
#pragma unroll
            for (int nf = 0; nf < 8; nf++) {
                mma_bf16(acc[mf][nf], ah[mf], bh[nf]);
                mma_bf16(acc[mf][nf], ah[mf], bl[nf]);
                mma_bf16(acc[mf][nf], al[mf], bh[nf]);
            }
    }

    // ---- epilogue: bias, (stats | relu), direct fragment stores ----
    int r0 = block_row + warp_m * 32 + (lane >> 2);   // rows r0, r0+8, r0+16, r0+24
#pragma unroll
    for (int nf = 0; nf < 8; nf++) {
        int col = warp_n * 64 + nf * 8 + (lane & 3) * 2;
        float b0 = __ldg(bias + col), b1 = __ldg(bias + col + 1);
        float v[4][2];
#pragma unroll
        for (int mf = 0; mf < 2; mf++) {
            v[mf * 2][0] = acc[mf][nf][0] + b0;
            v[mf * 2][1] = acc[mf][nf][1] + b1;
            v[mf * 2 + 1][0] = acc[mf][nf][2] + b0;
            v[mf * 2 + 1][1] = acc[mf][nf][3] + b1;
        }
        bool val[4];
        val[0] = r0 < n; val[1] = r0 + 8 < n; val[2] = r0 + 16 < n; val[3] = r0 + 24 < n;
        if (MODE == 0) {
            float s0 = 0.f, s1 = 0.f, q0 = 0.f, q1 = 0.f;
#pragma unroll
            for (int p = 0; p < 4; p++) {
                if (val[p]) {
                    s0 += v[p][0]; q0 += v[p][0] * v[p][0];
                    s1 += v[p][1]; q1 += v[p][1] * v[p][1];
                }
            }
#pragma unroll
            for (int d = 4; d < 32; d <<= 1) {
                s0 += __shfl_xor_sync(0xFFFFFFFFu, s0, d);
                s1 += __shfl_xor_sync(0xFFFFFFFFu, s1, d);
                q0 += __shfl_xor_sync(0xFFFFFFFFu, q0, d);
                q1 += __shfl_xor_sync(0xFFFFFFFFu, q1, d);
            }
            if (lane < 4) {
                int c0 = warp_n * 64 + nf * 8 + lane * 2;
                atomicAdd(&g_stats[c0], s0);
                atomicAdd(&g_stats[c0 + 1], s1);
                atomicAdd(&g_stats[HD + c0], q0);
                atomicAdd(&g_stats[HD + c0 + 1], q1);
            }
        } else {
#pragma unroll
            for (int p = 0; p < 4; p++) {
                v[p][0] = fmaxf(v[p][0], 0.f);
                v[p][1] = fmaxf(v[p][1], 0.f);
            }
        }
        // stores: rows r0 + {0,8,16,24}
#pragma unroll
        for (int p = 0; p < 4; p++) {
            int row = r0 + ((p & 1) ? 8 : 0) + ((p >> 1) ? 16 : 0);
            int pi = (p & 1) + (p >> 1) * 2;   // map store order to v index
            if (row < n) {
                float2 o = make_float2(v[pi][0], v[pi][1]);
                *reinterpret_cast<float2*>(Cout + (size_t)row * HD + col) = o;
            }
        }
    }
}

// ---------------- BN parameter computation ------------------------------------
__global__ void bn_params_kernel(const float* __restrict__ gamma,
                                 const float* __restrict__ beta, int n) {
    int h = threadIdx.x;
    float invn = 1.f / (float)n;
    float mu = g_stats[h] * invn;
    float var = g_stats[HD + h] * invn - mu * mu;
    float s = gamma[h] * rsqrtf(var + 1e-5f);
    g_scale[h] = s;
    g_shift[h] = beta[h] - mu * s;
}

// ---------------- pooling ------------------------------------------------------
__global__ void pool_kernel(const void* __restrict__ batch, int n, int sel) {
    int i = blockIdx.x * (blockDim.x >> 5) + (threadIdx.x >> 5);
    if (i >= n) return;
    int lane = threadIdx.x & 31;
    int is64 = g_idx64;
    const float* x = sel ? g_xB : g_xA;
    long long g = load_index(batch, i, is64);
    float4 v = *reinterpret_cast<const float4*>(x + (size_t)i * HD + lane * 4);
    red_add_v4(g_pool + g * HD + lane * 4, v);
    if (lane == 0) atomicAdd(&g_cnt[g], 1.f);
}

// ---------------- classifier head ----------------------------------------------
__global__ void head_kernel(const float* __restrict__ Wc,
                            const float* __restrict__ bc,
                            float* __restrict__ out) {
    int g = blockIdx.x;
    int h = threadIdx.x;
    float cnt = g_cnt[g];
    float v = g_pool[g * HD + h] / fmaxf(cnt, 1.f);
    __shared__ float sh[HD];
    for (int c = 0; c < NCLS; c++) {
        sh[h] = v * Wc[h * NCLS + c];
        __syncthreads();
        for (int s = 64; s > 0; s >>= 1) {
            if (h < s) sh[h] += sh[h + s];
            __syncthreads();
        }
        if (h == 0) out[g * NCLS + c] = sh[0] + bc[c];
        __syncthreads();
    }
}

// ---------------- launch ---------------------------------------------------------
extern "C" void kernel_launch(void* const* d_in, const int* in_sizes, int n_in,
                              void* d_out, int out_size) {
    cudaFuncSetAttribute(tgemm_kernel<0>,
                         cudaFuncAttributeMaxDynamicSharedMemorySize, SMEM_SZ);
    cudaFuncSetAttribute(tgemm_kernel<1>,
                         cudaFuncAttributeMaxDynamicSharedMemorySize, SMEM_SZ);

    // Detect input ordering: signature order has edge_index (1.6M elems) at [1];
    // setup_inputs dict order has node_centrality (50K) at [1].
    int ix, iei, ib, inc_, iec, iw1, ib1, ig1, ibe1, iw2, ib2, iwc, ibc;
    ix = 0;
    if (n_in >= 13 && in_sizes[1] > 1000000) {
        iei = 1; ib = 2; inc_ = 3; iec = 4;
        iw1 = 5; ib1 = 6; ig1 = 7; ibe1 = 8;
        iw2 = 9; ib2 = 10; iwc = 11; ibc = 12;
    } else {
        inc_ = 1; iec = 2; iw1 = 3; ib1 = 4; ig1 = 5; ibe1 = 6;
        iw2 = 7; ib2 = 8; iwc = 9; ibc = 10; iei = 11; ib = 12;
    }

    const float* x   = (const float*)d_in[ix];
    const void*  ei  = d_in[iei];
    const void*  bat = d_in[ib];
    const float* nc  = (const float*)d_in[inc_];
    const float* ec  = (const float*)d_in[iec];
    const float* W1  = (const float*)d_in[iw1];
    const float* b1  = (const float*)d_in[ib1];
    const float* g1  = (const float*)d_in[ig1];
    const float* be1 = (const float*)d_in[ibe1];
    const float* W2  = (const float*)d_in[iw2];
    const float* b2  = (const float*)d_in[ib2];
    const float* Wc  = (const float*)d_in[iwc];
    const float* bc  = (const float*)d_in[ibc];
    float* out = (float*)d_out;

    int n = in_sizes[ix] / HD;
    int E = in_sizes[iei] / 2;
    int n4 = n * (HD / 4);

    detect_idx_kernel<<<1, 32>>>(ei, E, n);
    copy_x_kernel<<<512, 256>>>((const float4*)x, n4);
    conv_w_all_kernel<<<(6 * HD * HD + 255) / 256, 256>>>(W1, W2);

    int gemm_blocks = (n + 127) / 128;
    int edge_blocks = (E + EB - 1) / EB;
    int pool_blocks = (n + 7) / 8;

    for (int l = 0; l < 3; l++) {
        int sel_in = l & 1;        // l=0: in A, l=1: in B, l=2: in A
        int sel_out = sel_in ^ 1;
        zero_agg_stats_kernel<<<2048, 256>>>(n4);
        edge_agg_kernel<<<edge_blocks, 256>>>(ei, ec, E, sel_in);
        tgemm_kernel<0><<<gemm_blocks, 256, SMEM_SZ>>>(nc, b1 + l * HD, n, sel_in, l);
        bn_params_kernel<<<1, HD>>>(g1 + l * HD, be1 + l * HD, n);
        tgemm_kernel<1><<<gemm_blocks, 256, SMEM_SZ>>>(b2 ? nullptr : nullptr, b2 + l * HD, n, sel_out, 3 + l);
    }

    zero_pool_kernel<<<64, 256>>>();
    pool_kernel<<<pool_blocks, 256>>>(bat, n, 1);  // final activations live in g_xB
    head_kernel<<<NG, HD>>>(Wc, bc, out);
}

// round 7
// speedup vs baseline: 12.5869x; 1.1419x over previous
#include <cuda_runtime.h>
#include <cuda_bf16.h>
#include <cstdint>

#define NMAX 50000
#define EMAX 800000
#define HD 128
#define NG 128
#define NCLS 10
#define BPAD 136                      // padded row stride (bf16 elems), 272B: conflict-free ldmatrix
#define EB 128                        // edges staged per block (fallback path)

// ---------------- scratch (device globals; no runtime allocation) -----------
// NOTE: referenced ONLY from device code (selected via int selectors).
// Passing their addresses from host code caused the round-4/5 5.9ms regression.
__device__ float g_xA[NMAX * HD];
__device__ float g_xB[NMAX * HD];
__device__ float g_agg[NMAX * HD];
__device__ float g_h1[NMAX * HD];
__device__ float g_stats[2 * HD];   // [0:128) col sums, [128:256) col sumsq
__device__ float g_scale[HD];
__device__ float g_shift[HD];
__device__ float g_pool[NG * HD];
__device__ float g_cnt[NG];
__device__ int   g_idx64;           // 1 if indices are int64, 0 if int32
// CSR of the (static) edge set, built once per call
__device__ int   g_deg[NMAX + 1];
__device__ int   g_off[NMAX + 1];
__device__ int   g_cursor[NMAX];
__device__ int   g_bsum[128];
__device__ int   g_csr_src[EMAX];
__device__ float g_csr_w[EMAX];
// pre-split weights in the padded SMEM image: [k][n], row stride BPAD
__device__ __nv_bfloat16 g_Whi[6][HD * BPAD];
__device__ __nv_bfloat16 g_Wlo[6][HD * BPAD];

// ---------------- helpers -----------------------------------------------------
__device__ __forceinline__ uint32_t smem_u32(const void* p) {
    uint32_t a;
    asm("{ .reg .u64 t; cvta.to.shared.u64 t, %1; cvt.u32.u64 %0, t; }"
        : "=r"(a) : "l"(p));
    return a;
}
__device__ __forceinline__ void red_add_v4(float* p, float4 v) {
    asm volatile("red.global.add.v4.f32 [%0], {%1,%2,%3,%4};"
                 :: "l"(p), "f"(v.x), "f"(v.y), "f"(v.z), "f"(v.w)
                 : "memory");
}
__device__ __forceinline__ uint32_t pack_bf(__nv_bfloat16 a, __nv_bfloat16 b) {
    uint16_t ua = *(uint16_t*)&a, ub = *(uint16_t*)&b;
    return (uint32_t)ua | ((uint32_t)ub << 16);
}
__device__ __forceinline__ void ldmatrix_x4(uint32_t* r, uint32_t addr) {
    asm volatile("ldmatrix.sync.aligned.m8n8.x4.shared.b16 {%0,%1,%2,%3}, [%4];"
                 : "=r"(r[0]), "=r"(r[1]), "=r"(r[2]), "=r"(r[3]) : "r"(addr));
}
__device__ __forceinline__ void ldmatrix_x4_trans(uint32_t* r, uint32_t addr) {
    asm volatile("ldmatrix.sync.aligned.m8n8.x4.trans.shared.b16 {%0,%1,%2,%3}, [%4];"
                 : "=r"(r[0]), "=r"(r[1]), "=r"(r[2]), "=r"(r[3]) : "r"(addr));
}
__device__ __forceinline__ void mma_bf16(float* c, const uint32_t* a, const uint32_t* b) {
    asm volatile(
        "mma.sync.aligned.m16n8k16.row.col.f32.bf16.bf16.f32 "
        "{%0,%1,%2,%3}, {%4,%5,%6,%7}, {%8,%9}, {%0,%1,%2,%3};"
        : "+f"(c[0]), "+f"(c[1]), "+f"(c[2]), "+f"(c[3])
        : "r"(a[0]), "r"(a[1]), "r"(a[2]), "r"(a[3]), "r"(b[0]), "r"(b[1]));
}

// ---------------- index dtype detect ------------------------------------------
__global__ void detect_idx_kernel(const void* ei, int E, int n) {
    if (threadIdx.x != 0 || blockIdx.x != 0) return;
    const long long* p64 = (const long long*)ei;
    int ok64 = 1;
    for (int i = 0; i < 16; i++) {
        long long v = p64[i];
        if (v < 0 || v >= (long long)n) { ok64 = 0; break; }
    }
    if (ok64) {
        for (int i = 0; i < 16; i++) {
            long long v = p64[(size_t)E + i];
            if (v < 0 || v >= (long long)n) { ok64 = 0; break; }
        }
    }
    g_idx64 = ok64;
}
__device__ __forceinline__ long long load_index(const void* base, long long off, int is64) {
    if (is64) return ((const long long*)base)[off];
    return (long long)((const int*)base)[off];
}

// ---------------- small utility kernels --------------------------------------
__global__ void copy_x_kernel(const float4* __restrict__ src, int n4) {
    float4* dst = reinterpret_cast<float4*>(g_xA);
    for (int i = blockIdx.x * blockDim.x + threadIdx.x; i < n4;
         i += gridDim.x * blockDim.x)
        dst[i] = src[i];
}
__global__ void zero_deg_stats_kernel(int n) {
    int i = blockIdx.x * blockDim.x + threadIdx.x;
    if (i <= n) g_deg[i] = 0;
    if (i < 2 * HD) g_stats[i] = 0.f;
}
__global__ void zero_pool_kernel() {
    int i = blockIdx.x * blockDim.x + threadIdx.x;
    if (i < NG * HD) g_pool[i] = 0.f;
    if (i < NG) g_cnt[i] = 0.f;
}
__global__ void zero_agg_stats_kernel(int n4) {   // fallback path only
    int i = blockIdx.x * blockDim.x + threadIdx.x;
    if (i < 2 * HD) g_stats[i] = 0.f;
    float4 z = make_float4(0.f, 0.f, 0.f, 0.f);
    float4* a = reinterpret_cast<float4*>(g_agg);
    for (int j = i; j < n4; j += gridDim.x * blockDim.x) a[j] = z;
}

// ---------------- weight pre-split (all 6 slots in one launch) -----------------
__global__ void conv_w_all_kernel(const float* __restrict__ W1,
                                  const float* __restrict__ W2) {
    int i = blockIdx.x * blockDim.x + threadIdx.x;
    if (i >= 6 * HD * HD) return;
    int slot = i >> 14;
    int j = i & (HD * HD - 1);
    int n = j & 127, k = j >> 7;
    const float* W = (slot < 3) ? (W1 + (size_t)slot * HD * HD)
                                : (W2 + (size_t)(slot - 3) * HD * HD);
    float w = W[k * HD + n];
    __nv_bfloat16 hi = __float2bfloat16(w);
    float lof = w - __bfloat162float(hi);
    g_Whi[slot][k * BPAD + n] = hi;
    g_Wlo[slot][k * BPAD + n] = __float2bfloat16(lof);
}

// ---------------- CSR construction (once per call) -----------------------------
__global__ void hist_kernel(const void* __restrict__ ei, int E) {
    int is64 = g_idx64;
    for (long long e = blockIdx.x * blockDim.x + threadIdx.x; e < E;
         e += (long long)gridDim.x * blockDim.x) {
        int d = (int)load_index(ei, (long long)E + e, is64);
        atomicAdd(&g_deg[d], 1);
    }
}
// block-wise inclusive scan over 512-chunks of deg -> exclusive offsets + chunk sums
__global__ void scan1_kernel(int n) {
    __shared__ int sh[512];
    int t = threadIdx.x;
    int i = blockIdx.x * 512 + t;
    int v = (i < n) ? g_deg[i] : 0;
    sh[t] = v;
    __syncthreads();
#pragma unroll
    for (int o = 1; o < 512; o <<= 1) {
        int tmp = (t >= o) ? sh[t - o] : 0;
        __syncthreads();
        sh[t] += tmp;
        __syncthreads();
    }
    if (i < n) g_off[i] = sh[t] - v;        // exclusive within chunk
    if (t == 511) g_bsum[blockIdx.x] = sh[511];
}
__global__ void scan2_kernel(int nchunks, int E, int n) {
    __shared__ int sh[512];
    int t = threadIdx.x;
    int v = (t < nchunks) ? g_bsum[t] : 0;
    sh[t] = v;
    __syncthreads();
#pragma unroll
    for (int o = 1; o < 512; o <<= 1) {
        int tmp = (t >= o) ? sh[t - o] : 0;
        __syncthreads();
        sh[t] += tmp;
        __syncthreads();
    }
    if (t < nchunks) g_bsum[t] = sh[t] - v; // exclusive chunk offsets
    if (t == 0) g_off[n] = E;
}
__global__ void scan3_kernel(int n) {
    int i = blockIdx.x * blockDim.x + threadIdx.x;
    if (i < n) {
        int o = g_off[i] + g_bsum[i >> 9];
        g_off[i] = o;
        g_cursor[i] = o;
    }
}
__global__ void scatter_kernel(const void* __restrict__ ei,
                               const float* __restrict__ ec, int E) {
    int is64 = g_idx64;
    for (long long e = blockIdx.x * blockDim.x + threadIdx.x; e < E;
         e += (long long)gridDim.x * blockDim.x) {
        int s = (int)load_index(ei, e, is64);
        int d = (int)load_index(ei, (long long)E + e, is64);
        float w = __ldg(ec + e);
        int pos = atomicAdd(&g_cursor[d], 1);
        g_csr_src[pos] = s;
        g_csr_w[pos] = w;
    }
}

// ---------------- CSR aggregation: agg[v] = sum_j x[src_j] * w_j ---------------
// Warp per node; registers accumulate; one 512B store per node (no atomics).
__global__ __launch_bounds__(256, 4)
void csr_agg_kernel(int n, int sel) {
    int v = blockIdx.x * 8 + (threadIdx.x >> 5);
    if (v >= n) return;
    int lane = threadIdx.x & 31;
    const float* x = sel ? g_xB : g_xA;
    int j = g_off[v], end = g_off[v + 1];
    float4 acc = make_float4(0.f, 0.f, 0.f, 0.f);
    if (j < end) {
        int s = __ldg(g_csr_src + j);
        float w = __ldg(g_csr_w + j);
        float4 vv = *reinterpret_cast<const float4*>(x + (size_t)s * HD + lane * 4);
        for (;;) {
            int jn = j + 1;
            float4 vn; float wn;
            if (jn < end) {
                int sn = __ldg(g_csr_src + jn);
                wn = __ldg(g_csr_w + jn);
                vn = *reinterpret_cast<const float4*>(x + (size_t)sn * HD + lane * 4);
            }
            acc.x = fmaf(vv.x, w, acc.x);
            acc.y = fmaf(vv.y, w, acc.y);
            acc.z = fmaf(vv.z, w, acc.z);
            acc.w = fmaf(vv.w, w, acc.w);
            if (jn >= end) break;
            vv = vn; w = wn; j = jn;
        }
    }
    *reinterpret_cast<float4*>(g_agg + (size_t)v * HD + lane * 4) = acc;
}

// ---------------- fallback edge aggregation (atomic path, E > EMAX) ------------
__global__ __launch_bounds__(256, 4)
void edge_agg_kernel(const void* __restrict__ ei,
                     const float* __restrict__ ec,
                     int E, int sel) {
    __shared__ int s_src[EB];
    __shared__ int s_dst[EB];
    __shared__ float s_w[EB];
    int tid = threadIdx.x, wid = tid >> 5, lane = tid & 31;
    int is64 = g_idx64;
    const float* x = sel ? g_xB : g_xA;

    long long base = (long long)blockIdx.x * EB;
    if (base >= E) return;
    int cnt = min(EB, (int)(E - base));
    if (tid < cnt) {
        s_src[tid] = (int)load_index(ei, base + tid, is64);
        s_dst[tid] = (int)load_index(ei, (long long)E + base + tid, is64);
        s_w[tid] = __ldg(ec + base + tid);
    }
    __syncthreads();

    int e = wid;
    if (e < cnt) {
        int s = s_src[e];
        float4 v = *reinterpret_cast<const float4*>(x + (size_t)s * HD + lane * 4);
        while (true) {
            int en = e + 8;
            float4 vn;
            if (en < cnt) {
                int sn = s_src[en];
                vn = *reinterpret_cast<const float4*>(x + (size_t)sn * HD + lane * 4);
            }
            float w = s_w[e];
            int d = s_dst[e];
            float4 o = make_float4(v.x * w, v.y * w, v.z * w, v.w * w);
            red_add_v4(g_agg + (size_t)d * HD + lane * 4, o);
            if (en >= cnt) break;
            v = vn; e = en;
        }
    }
}

// ---------------- tensor-core bf16x3 fused GEMM (one tile per CTA) -------------
// MODE 0: A = x_in + agg * nc[row];  C = h1 = A @ W1 + b1; accumulate col stats
// MODE 1: A = relu(h1 * scale[k] + shift[k]); C = x_out = relu(A @ W2 + b2)
#define TILE_BYTES (HD * BPAD * 2)          // 34816
#define S_AHI 0
#define S_ALO TILE_BYTES
#define S_BHI (2 * TILE_BYTES)
#define S_BLO (3 * TILE_BYTES)
#define SMEM_SZ (4 * TILE_BYTES)            // 139264

template <int MODE>
__global__ __launch_bounds__(256, 1)
void tgemm_kernel(const float* __restrict__ nc,
                  const float* __restrict__ bias,
                  int n, int sel, int slot) {
    extern __shared__ char smem[];
    uint32_t sb = smem_u32(smem);
    int tid = threadIdx.x, wid = tid >> 5, lane = tid & 31;
    int block_row = blockIdx.x * 128;
    int warp_m = wid & 3;                    // rows warp_m*32
    int warp_n = wid >> 2;                   // cols warp_n*64

    const float* Ain;
    float* Cout;
    if (MODE == 0) { Ain = sel ? g_xB : g_xA; Cout = g_h1; }
    else           { Ain = g_h1;              Cout = sel ? g_xB : g_xA; }

    // ---- copy pre-split W tiles (already padded image) ----
    {
        const uint4* wh = (const uint4*)g_Whi[slot];
        const uint4* wl = (const uint4*)g_Wlo[slot];
        uint4* dh = (uint4*)(smem + S_BHI);
        uint4* dl = (uint4*)(smem + S_BLO);
        for (int i = tid; i < TILE_BYTES / 16; i += 256) {
            dh[i] = wh[i];
            dl[i] = wl[i];
        }
    }

    // ---- fused A producer: load, fuse, bf16 hi/lo split ----
#pragma unroll 4
    for (int it = 0; it < 16; it++) {
        int f = tid + it * 256;              // 0..4095 float4 slots
        int row = f >> 5;                    // 0..127
        int kk = (f & 31) << 2;              // 0..124
        int grow = block_row + row;
        float4 v = make_float4(0.f, 0.f, 0.f, 0.f);
        if (grow < n) {
            v = *reinterpret_cast<const float4*>(Ain + (size_t)grow * HD + kk);
            if (MODE == 0) {
                float w = __ldg(nc + grow);
                float4 u = *reinterpret_cast<const float4*>(g_agg + (size_t)grow * HD + kk);
                v.x = fmaf(u.x, w, v.x);
                v.y = fmaf(u.y, w, v.y);
                v.z = fmaf(u.z, w, v.z);
                v.w = fmaf(u.w, w, v.w);
            } else {
                float4 sc = *reinterpret_cast<const float4*>(g_scale + kk);
                float4 sh = *reinterpret_cast<const float4*>(g_shift + kk);
                v.x = fmaxf(fmaf(v.x, sc.x, sh.x), 0.f);
                v.y = fmaxf(fmaf(v.y, sc.y, sh.y), 0.f);
                v.z = fmaxf(fmaf(v.z, sc.z, sh.z), 0.f);
                v.w = fmaxf(fmaf(v.w, sc.w, sh.w), 0.f);
            }
        }
        __nv_bfloat16 h0 = __float2bfloat16(v.x);
        __nv_bfloat16 h1 = __float2bfloat16(v.y);
        __nv_bfloat16 h2 = __float2bfloat16(v.z);
        __nv_bfloat16 h3 = __float2bfloat16(v.w);
        __nv_bfloat16 l0 = __float2bfloat16(v.x - __bfloat162float(h0));
        __nv_bfloat16 l1 = __float2bfloat16(v.y - __bfloat162float(h1));
        __nv_bfloat16 l2 = __float2bfloat16(v.z - __bfloat162float(h2));
        __nv_bfloat16 l3 = __float2bfloat16(v.w - __bfloat162float(h3));
        uint2 hp; hp.x = pack_bf(h0, h1); hp.y = pack_bf(h2, h3);
        uint2 lp; lp.x = pack_bf(l0, l1); lp.y = pack_bf(l2, l3);
        int off = row * (BPAD * 2) + kk * 2;     // bytes
        *(uint2*)(smem + S_AHI + off) = hp;
        *(uint2*)(smem + S_ALO + off) = lp;
    }
    __syncthreads();

    // ---- MMA mainloop: 8 k-steps, 3 products, fp32 accumulate ----
    float acc[2][8][4];
#pragma unroll
    for (int mf = 0; mf < 2; mf++)
#pragma unroll
        for (int nf = 0; nf < 8; nf++)
#pragma unroll
            for (int q = 0; q < 4; q++) acc[mf][nf][q] = 0.f;

    int lrow = lane & 15;
    int lblk = (lane >> 4) * 16;
    uint32_t aBase = sb + (warp_m * 32 + lrow) * (BPAD * 2) + lblk;
    uint32_t bBase = sb + lrow * (BPAD * 2) + (warp_n * 64) * 2 + lblk;

#pragma unroll
    for (int ks = 0; ks < 8; ks++) {
        uint32_t ah[2][4], al[2][4], bh[8][2], bl[8][2];
#pragma unroll
        for (int mf = 0; mf < 2; mf++) {
            uint32_t addr = aBase + mf * 16 * (BPAD * 2) + ks * 32;
            ldmatrix_x4(ah[mf], addr + S_AHI);
            ldmatrix_x4(al[mf], addr + S_ALO);
        }
#pragma unroll
        for (int nb = 0; nb < 4; nb++) {
            uint32_t addr = bBase + ks * 16 * (BPAD * 2) + nb * 32;
            uint32_t rh[4], rl[4];
            ldmatrix_x4_trans(rh, addr + S_BHI);
            ldmatrix_x4_trans(rl, addr + S_BLO);
            bh[2 * nb][0] = rh[0]; bh[2 * nb][1] = rh[1];
            bh[2 * nb + 1][0] = rh[2]; bh[2 * nb + 1][1] = rh[3];
            bl[2 * nb][0] = rl[0]; bl[2 * nb][1] = rl[1];
            bl[2 * nb + 1][0] = rl[2]; bl[2 * nb + 1][1] = rl[3];
        }
#pragma unroll
        for (int mf = 0; mf < 2; mf++)
#pragma unroll
            for (int nf = 0; nf < 8; nf++) {
                mma_bf16(acc[mf][nf], ah[mf], bh[nf]);
                mma_bf16(acc[mf][nf], ah[mf], bl[nf]);
                mma_bf16(acc[mf][nf], al[mf], bh[nf]);
            }
    }

    // ---- epilogue: bias, (stats | relu), direct fragment stores ----
    int r0 = block_row + warp_m * 32 + (lane >> 2);
#pragma unroll
    for (int nf = 0; nf < 8; nf++) {
        int col = warp_n * 64 + nf * 8 + (lane & 3) * 2;
        float b0 = __ldg(bias + col), b1 = __ldg(bias + col + 1);
        float v[4][2];
#pragma unroll
        for (int mf = 0; mf < 2; mf++) {
            v[mf * 2][0] = acc[mf][nf][0] + b0;
            v[mf * 2][1] = acc[mf][nf][1] + b1;
            v[mf * 2 + 1][0] = acc[mf][nf][2] + b0;
            v[mf * 2 + 1][1] = acc[mf][nf][3] + b1;
        }
        bool val[4];
        val[0] = r0 < n; val[1] = r0 + 8 < n; val[2] = r0 + 16 < n; val[3] = r0 + 24 < n;
        if (MODE == 0) {
            float s0 = 0.f, s1 = 0.f, q0 = 0.f, q1 = 0.f;
#pragma unroll
            for (int p = 0; p < 4; p++) {
                if (val[p]) {
                    s0 += v[p][0]; q0 += v[p][0] * v[p][0];
                    s1 += v[p][1]; q1 += v[p][1] * v[p][1];
                }
            }
#pragma unroll
            for (int d = 4; d < 32; d <<= 1) {
                s0 += __shfl_xor_sync(0xFFFFFFFFu, s0, d);
                s1 += __shfl_xor_sync(0xFFFFFFFFu, s1, d);
                q0 += __shfl_xor_sync(0xFFFFFFFFu, q0, d);
                q1 += __shfl_xor_sync(0xFFFFFFFFu, q1, d);
            }
            if (lane < 4) {
                int c0 = warp_n * 64 + nf * 8 + lane * 2;
                atomicAdd(&g_stats[c0], s0);
                atomicAdd(&g_stats[c0 + 1], s1);
                atomicAdd(&g_stats[HD + c0], q0);
                atomicAdd(&g_stats[HD + c0 + 1], q1);
            }
        } else {
#pragma unroll
            for (int p = 0; p < 4; p++) {
                v[p][0] = fmaxf(v[p][0], 0.f);
                v[p][1] = fmaxf(v[p][1], 0.f);
            }
        }
#pragma unroll
        for (int p = 0; p < 4; p++) {
            int row = r0 + ((p & 1) ? 8 : 0) + ((p >> 1) ? 16 : 0);
            int pi = (p & 1) + (p >> 1) * 2;
            if (row < n) {
                float2 o = make_float2(v[pi][0], v[pi][1]);
                *reinterpret_cast<float2*>(Cout + (size_t)row * HD + col) = o;
            }
        }
    }
}

// ---------------- BN parameter computation (self-resetting stats) --------------
__global__ void bn_params_kernel(const float* __restrict__ gamma,
                                 const float* __restrict__ beta, int n) {
    int h = threadIdx.x;
    float invn = 1.f / (float)n;
    float mu = g_stats[h] * invn;
    float var = g_stats[HD + h] * invn - mu * mu;
    float s = gamma[h] * rsqrtf(var + 1e-5f);
    g_scale[h] = s;
    g_shift[h] = beta[h] - mu * s;
    g_stats[h] = 0.f;                 // reset for next layer's tgemm<0>
    g_stats[HD + h] = 0.f;
}

// ---------------- pooling ------------------------------------------------------
__global__ void pool_kernel(const void* __restrict__ batch, int n, int sel) {
    int i = blockIdx.x * (blockDim.x >> 5) + (threadIdx.x >> 5);
    if (i >= n) return;
    int lane = threadIdx.x & 31;
    int is64 = g_idx64;
    const float* x = sel ? g_xB : g_xA;
    long long g = load_index(batch, i, is64);
    float4 v = *reinterpret_cast<const float4*>(x + (size_t)i * HD + lane * 4);
    red_add_v4(g_pool + g * HD + lane * 4, v);
    if (lane == 0) atomicAdd(&g_cnt[g], 1.f);
}

// ---------------- classifier head ----------------------------------------------
__global__ void head_kernel(const float* __restrict__ Wc,
                            const float* __restrict__ bc,
                            float* __restrict__ out) {
    int g = blockIdx.x;
    int h = threadIdx.x;
    float cnt = g_cnt[g];
    float v = g_pool[g * HD + h] / fmaxf(cnt, 1.f);
    __shared__ float sh[HD];
    for (int c = 0; c < NCLS; c++) {
        sh[h] = v * Wc[h * NCLS + c];
        __syncthreads();
        for (int s = 64; s > 0; s >>= 1) {
            if (h < s) sh[h] += sh[h + s];
            __syncthreads();
        }
        if (h == 0) out[g * NCLS + c] = sh[0] + bc[c];
        __syncthreads();
    }
}

// ---------------- launch ---------------------------------------------------------
extern "C" void kernel_launch(void* const* d_in, const int* in_sizes, int n_in,
                              void* d_out, int out_size) {
    cudaFuncSetAttribute(tgemm_kernel<0>,
                         cudaFuncAttributeMaxDynamicSharedMemorySize, SMEM_SZ);
    cudaFuncSetAttribute(tgemm_kernel<1>,
                         cudaFuncAttributeMaxDynamicSharedMemorySize, SMEM_SZ);

    // Detect input ordering: signature order has edge_index (1.6M elems) at [1];
    // setup_inputs dict order has node_centrality (50K) at [1].
    int ix, iei, ib, inc_, iec, iw1, ib1, ig1, ibe1, iw2, ib2, iwc, ibc;
    ix = 0;
    if (n_in >= 13 && in_sizes[1] > 1000000) {
        iei = 1; ib = 2; inc_ = 3; iec = 4;
        iw1 = 5; ib1 = 6; ig1 = 7; ibe1 = 8;
        iw2 = 9; ib2 = 10; iwc = 11; ibc = 12;
    } else {
        inc_ = 1; iec = 2; iw1 = 3; ib1 = 4; ig1 = 5; ibe1 = 6;
        iw2 = 7; ib2 = 8; iwc = 9; ibc = 10; iei = 11; ib = 12;
    }

    const float* x   = (const float*)d_in[ix];
    const void*  ei  = d_in[iei];
    const void*  bat = d_in[ib];
    const float* nc  = (const float*)d_in[inc_];
    const float* ec  = (const float*)d_in[iec];
    const float* W1  = (const float*)d_in[iw1];
    const float* b1  = (const float*)d_in[ib1];
    const float* g1  = (const float*)d_in[ig1];
    const float* be1 = (const float*)d_in[ibe1];
    const float* W2  = (const float*)d_in[iw2];
    const float* b2  = (const float*)d_in[ib2];
    const float* Wc  = (const float*)d_in[iwc];
    const float* bc  = (const float*)d_in[ibc];
    float* out = (float*)d_out;

    int n = in_sizes[ix] / HD;
    int E = in_sizes[iei] / 2;
    int n4 = n * (HD / 4);
    bool use_csr = (E <= EMAX) && (n <= NMAX);

    detect_idx_kernel<<<1, 32>>>(ei, E, n);
    copy_x_kernel<<<512, 256>>>((const float4*)x, n4);
    conv_w_all_kernel<<<(6 * HD * HD + 255) / 256, 256>>>(W1, W2);

    int gemm_blocks = (n + 127) / 128;
    int pool_blocks = (n + 7) / 8;

    if (use_csr) {
        int nchunks = (n + 511) / 512;
        zero_deg_stats_kernel<<<(n + 256) / 256, 256>>>(n);
        hist_kernel<<<512, 256>>>(ei, E);
        scan1_kernel<<<nchunks, 512>>>(n);
        scan2_kernel<<<1, 512>>>(nchunks, E, n);
        scan3_kernel<<<(n + 255) / 256, 256>>>(n);
        scatter_kernel<<<512, 256>>>(ei, ec, E);
    }

    int agg_blocks = (n + 7) / 8;
    int edge_blocks = (E + EB - 1) / EB;

    for (int l = 0; l < 3; l++) {
        int sel_in = l & 1;        // l=0: in A, l=1: in B, l=2: in A
        int sel_out = sel_in ^ 1;
        if (use_csr) {
            csr_agg_kernel<<<agg_blocks, 256>>>(n, sel_in);
        } else {
            zero_agg_stats_kernel<<<2048, 256>>>(n4);
            edge_agg_kernel<<<edge_blocks, 256>>>(ei, ec, E, sel_in);
        }
        tgemm_kernel<0><<<gemm_blocks, 256, SMEM_SZ>>>(nc, b1 + l * HD, n, sel_in, l);
        bn_params_kernel<<<1, HD>>>(g1 + l * HD, be1 + l * HD, n);
        tgemm_kernel<1><<<gemm_blocks, 256, SMEM_SZ>>>(nullptr, b2 + l * HD, n, sel_out, 3 + l);
    }

    zero_pool_kernel<<<64, 256>>>();
    pool_kernel<<<pool_blocks, 256>>>(bat, n, 1);  // final activations live in g_xB
    head_kernel<<<NG, HD>>>(Wc, bc, out);
}

// round 8
// speedup vs baseline: 14.1956x; 1.1278x over previous
#include <cuda_runtime.h>
#include <cuda_bf16.h>
#include <cstdint>

#define NMAX 50000
#define EMAX 800000
#define HD 128
#define NG 128
#define NCLS 10
#define BPAD 136                      // padded row stride (bf16 elems), 272B: conflict-free ldmatrix
#define EB 128                        // edges staged per block (fallback path)

// ---------------- scratch (device globals; no runtime allocation) -----------
// NOTE: referenced ONLY from device code (selected via int selectors).
// Host-passed &g_x* resolves to host shadow memory (NVLink-C2C, 15-22x slow).
__device__ float g_xA[NMAX * HD];
__device__ float g_xB[NMAX * HD];
__device__ float g_agg[NMAX * HD];
__device__ float g_h1[NMAX * HD];
__device__ float g_stats[2 * HD];   // [0:128) col sums, [128:256) col sumsq
__device__ float g_scale[HD];
__device__ float g_shift[HD];
__device__ float g_pool[NG * HD];
__device__ float g_cnt[NG];
__device__ int   g_idx64;           // 1 if indices are int64, 0 if int32
// CSR of the (static) edge set, built once per call
__device__ int   g_deg[NMAX + 1];
__device__ int   g_off[NMAX + 1];
__device__ int   g_cursor[NMAX];
__device__ int   g_bsum[128];
__device__ int   g_csr_src[EMAX];
__device__ float g_csr_w[EMAX];
// pre-split weights in the padded SMEM image: [k][n], row stride BPAD
__device__ __nv_bfloat16 g_Whi[6][HD * BPAD];
__device__ __nv_bfloat16 g_Wlo[6][HD * BPAD];

// ---------------- helpers -----------------------------------------------------
__device__ __forceinline__ uint32_t smem_u32(const void* p) {
    uint32_t a;
    asm("{ .reg .u64 t; cvta.to.shared.u64 t, %1; cvt.u32.u64 %0, t; }"
        : "=r"(a) : "l"(p));
    return a;
}
__device__ __forceinline__ void red_add_v4(float* p, float4 v) {
    asm volatile("red.global.add.v4.f32 [%0], {%1,%2,%3,%4};"
                 :: "l"(p), "f"(v.x), "f"(v.y), "f"(v.z), "f"(v.w)
                 : "memory");
}
__device__ __forceinline__ uint32_t pack_bf(__nv_bfloat16 a, __nv_bfloat16 b) {
    uint16_t ua = *(uint16_t*)&a, ub = *(uint16_t*)&b;
    return (uint32_t)ua | ((uint32_t)ub << 16);
}
__device__ __forceinline__ void ldmatrix_x4(uint32_t* r, uint32_t addr) {
    asm volatile("ldmatrix.sync.aligned.m8n8.x4.shared.b16 {%0,%1,%2,%3}, [%4];"
                 : "=r"(r[0]), "=r"(r[1]), "=r"(r[2]), "=r"(r[3]) : "r"(addr));
}
__device__ __forceinline__ void ldmatrix_x4_trans(uint32_t* r, uint32_t addr) {
    asm volatile("ldmatrix.sync.aligned.m8n8.x4.trans.shared.b16 {%0,%1,%2,%3}, [%4];"
                 : "=r"(r[0]), "=r"(r[1]), "=r"(r[2]), "=r"(r[3]) : "r"(addr));
}
__device__ __forceinline__ void mma_bf16(float* c, const uint32_t* a, const uint32_t* b) {
    asm volatile(
        "mma.sync.aligned.m16n8k16.row.col.f32.bf16.bf16.f32 "
        "{%0,%1,%2,%3}, {%4,%5,%6,%7}, {%8,%9}, {%0,%1,%2,%3};"
        : "+f"(c[0]), "+f"(c[1]), "+f"(c[2]), "+f"(c[3])
        : "r"(a[0]), "r"(a[1]), "r"(a[2]), "r"(a[3]), "r"(b[0]), "r"(b[1]));
}

// ---------------- index dtype detect ------------------------------------------
__global__ void detect_idx_kernel(const void* ei, int E, int n) {
    if (threadIdx.x != 0 || blockIdx.x != 0) return;
    const long long* p64 = (const long long*)ei;
    int ok64 = 1;
    for (int i = 0; i < 16; i++) {
        long long v = p64[i];
        if (v < 0 || v >= (long long)n) { ok64 = 0; break; }
    }
    if (ok64) {
        for (int i = 0; i < 16; i++) {
            long long v = p64[(size_t)E + i];
            if (v < 0 || v >= (long long)n) { ok64 = 0; break; }
        }
    }
    g_idx64 = ok64;
}
__device__ __forceinline__ long long load_index(const void* base, long long off, int is64) {
    if (is64) return ((const long long*)base)[off];
    return (long long)((const int*)base)[off];
}

// ---------------- small utility kernels --------------------------------------
__global__ void copy_x_kernel(const float4* __restrict__ src, int n4) {
    float4* dst = reinterpret_cast<float4*>(g_xA);
    for (int i = blockIdx.x * blockDim.x + threadIdx.x; i < n4;
         i += gridDim.x * blockDim.x)
        dst[i] = src[i];
}
__global__ void zero_deg_stats_kernel(int n) {
    int i = blockIdx.x * blockDim.x + threadIdx.x;
    if (i <= n) g_deg[i] = 0;
    if (i < 2 * HD) g_stats[i] = 0.f;
}
__global__ void zero_pool_kernel() {
    int i = blockIdx.x * blockDim.x + threadIdx.x;
    if (i < NG * HD) g_pool[i] = 0.f;
    if (i < NG) g_cnt[i] = 0.f;
}
__global__ void zero_agg_stats_kernel(int n4) {   // fallback path only
    int i = blockIdx.x * blockDim.x + threadIdx.x;
    if (i < 2 * HD) g_stats[i] = 0.f;
    float4 z = make_float4(0.f, 0.f, 0.f, 0.f);
    float4* a = reinterpret_cast<float4*>(g_agg);
    for (int j = i; j < n4; j += gridDim.x * blockDim.x) a[j] = z;
}

// ---------------- weight pre-split (all 6 slots in one launch) -----------------
__global__ void conv_w_all_kernel(const float* __restrict__ W1,
                                  const float* __restrict__ W2) {
    int i = blockIdx.x * blockDim.x + threadIdx.x;
    if (i >= 6 * HD * HD) return;
    int slot = i >> 14;
    int j = i & (HD * HD - 1);
    int n = j & 127, k = j >> 7;
    const float* W = (slot < 3) ? (W1 + (size_t)slot * HD * HD)
                                : (W2 + (size_t)(slot - 3) * HD * HD);
    float w = W[k * HD + n];
    __nv_bfloat16 hi = __float2bfloat16(w);
    float lof = w - __bfloat162float(hi);
    g_Whi[slot][k * BPAD + n] = hi;
    g_Wlo[slot][k * BPAD + n] = __float2bfloat16(lof);
}

// ---------------- CSR construction (once per call) -----------------------------
__global__ void hist_kernel(const void* __restrict__ ei, int E) {
    int is64 = g_idx64;
    for (long long e = blockIdx.x * blockDim.x + threadIdx.x; e < E;
         e += (long long)gridDim.x * blockDim.x) {
        int d = (int)load_index(ei, (long long)E + e, is64);
        atomicAdd(&g_deg[d], 1);
    }
}
__global__ void scan1_kernel(int n) {
    __shared__ int sh[512];
    int t = threadIdx.x;
    int i = blockIdx.x * 512 + t;
    int v = (i < n) ? g_deg[i] : 0;
    sh[t] = v;
    __syncthreads();
#pragma unroll
    for (int o = 1; o < 512; o <<= 1) {
        int tmp = (t >= o) ? sh[t - o] : 0;
        __syncthreads();
        sh[t] += tmp;
        __syncthreads();
    }
    if (i < n) g_off[i] = sh[t] - v;        // exclusive within chunk
    if (t == 511) g_bsum[blockIdx.x] = sh[511];
}
__global__ void scan2_kernel(int nchunks, int E, int n) {
    __shared__ int sh[512];
    int t = threadIdx.x;
    int v = (t < nchunks) ? g_bsum[t] : 0;
    sh[t] = v;
    __syncthreads();
#pragma unroll
    for (int o = 1; o < 512; o <<= 1) {
        int tmp = (t >= o) ? sh[t - o] : 0;
        __syncthreads();
        sh[t] += tmp;
        __syncthreads();
    }
    if (t < nchunks) g_bsum[t] = sh[t] - v; // exclusive chunk offsets
    if (t == 0) g_off[n] = E;
}
__global__ void scan3_kernel(int n) {
    int i = blockIdx.x * blockDim.x + threadIdx.x;
    if (i < n) {
        int o = g_off[i] + g_bsum[i >> 9];
        g_off[i] = o;
        g_cursor[i] = o;
    }
}
__global__ void scatter_kernel(const void* __restrict__ ei,
                               const float* __restrict__ ec, int E) {
    int is64 = g_idx64;
    for (long long e = blockIdx.x * blockDim.x + threadIdx.x; e < E;
         e += (long long)gridDim.x * blockDim.x) {
        int s = (int)load_index(ei, e, is64);
        int d = (int)load_index(ei, (long long)E + e, is64);
        float w = __ldg(ec + e);
        int pos = atomicAdd(&g_cursor[d], 1);
        g_csr_src[pos] = s;
        g_csr_w[pos] = w;
    }
}

// ---------------- CSR aggregation: agg[v] = sum_j x[src_j] * w_j ---------------
// Warp per node; 4-wide batched gathers for MLP; one 512B store per node.
__global__ __launch_bounds__(256, 4)
void csr_agg_kernel(int n, int sel) {
    int v = blockIdx.x * 8 + (threadIdx.x >> 5);
    if (v >= n) return;
    int lane = threadIdx.x & 31;
    const float* x = sel ? g_xB : g_xA;
    int j = g_off[v], end = g_off[v + 1];
    float4 acc = make_float4(0.f, 0.f, 0.f, 0.f);

    for (; j + 4 <= end; j += 4) {
        int s0 = __ldg(g_csr_src + j);
        int s1 = __ldg(g_csr_src + j + 1);
        int s2 = __ldg(g_csr_src + j + 2);
        int s3 = __ldg(g_csr_src + j + 3);
        float w0 = __ldg(g_csr_w + j);
        float w1 = __ldg(g_csr_w + j + 1);
        float w2 = __ldg(g_csr_w + j + 2);
        float w3 = __ldg(g_csr_w + j + 3);
        float4 v0 = *reinterpret_cast<const float4*>(x + (size_t)s0 * HD + lane * 4);
        float4 v1 = *reinterpret_cast<const float4*>(x + (size_t)s1 * HD + lane * 4);
        float4 v2 = *reinterpret_cast<const float4*>(x + (size_t)s2 * HD + lane * 4);
        float4 v3 = *reinterpret_cast<const float4*>(x + (size_t)s3 * HD + lane * 4);
        acc.x = fmaf(v0.x, w0, acc.x); acc.y = fmaf(v0.y, w0, acc.y);
        acc.z = fmaf(v0.z, w0, acc.z); acc.w = fmaf(v0.w, w0, acc.w);
        acc.x = fmaf(v1.x, w1, acc.x); acc.y = fmaf(v1.y, w1, acc.y);
        acc.z = fmaf(v1.z, w1, acc.z); acc.w = fmaf(v1.w, w1, acc.w);
        acc.x = fmaf(v2.x, w2, acc.x); acc.y = fmaf(v2.y, w2, acc.y);
        acc.z = fmaf(v2.z, w2, acc.z); acc.w = fmaf(v2.w, w2, acc.w);
        acc.x = fmaf(v3.x, w3, acc.x); acc.y = fmaf(v3.y, w3, acc.y);
        acc.z = fmaf(v3.z, w3, acc.z); acc.w = fmaf(v3.w, w3, acc.w);
    }
    for (; j < end; j++) {
        int s = __ldg(g_csr_src + j);
        float w = __ldg(g_csr_w + j);
        float4 vv = *reinterpret_cast<const float4*>(x + (size_t)s * HD + lane * 4);
        acc.x = fmaf(vv.x, w, acc.x); acc.y = fmaf(vv.y, w, acc.y);
        acc.z = fmaf(vv.z, w, acc.z); acc.w = fmaf(vv.w, w, acc.w);
    }
    *reinterpret_cast<float4*>(g_agg + (size_t)v * HD + lane * 4) = acc;
}

// ---------------- fallback edge aggregation (atomic path, E > EMAX) ------------
__global__ __launch_bounds__(256, 4)
void edge_agg_kernel(const void* __restrict__ ei,
                     const float* __restrict__ ec,
                     int E, int sel) {
    __shared__ int s_src[EB];
    __shared__ int s_dst[EB];
    __shared__ float s_w[EB];
    int tid = threadIdx.x, wid = tid >> 5, lane = tid & 31;
    int is64 = g_idx64;
    const float* x = sel ? g_xB : g_xA;

    long long base = (long long)blockIdx.x * EB;
    if (base >= E) return;
    int cnt = min(EB, (int)(E - base));
    if (tid < cnt) {
        s_src[tid] = (int)load_index(ei, base + tid, is64);
        s_dst[tid] = (int)load_index(ei, (long long)E + base + tid, is64);
        s_w[tid] = __ldg(ec + base + tid);
    }
    __syncthreads();

    int e = wid;
    if (e < cnt) {
        int s = s_src[e];
        float4 v = *reinterpret_cast<const float4*>(x + (size_t)s * HD + lane * 4);
        while (true) {
            int en = e + 8;
            float4 vn;
            if (en < cnt) {
                int sn = s_src[en];
                vn = *reinterpret_cast<const float4*>(x + (size_t)sn * HD + lane * 4);
            }
            float w = s_w[e];
            int d = s_dst[e];
            float4 o = make_float4(v.x * w, v.y * w, v.z * w, v.w * w);
            red_add_v4(g_agg + (size_t)d * HD + lane * 4, o);
            if (en >= cnt) break;
            v = vn; e = en;
        }
    }
}

// ---------------- tensor-core bf16x3 fused GEMM (persistent, clean test) -------
// MODE 0: A = x_in + agg * nc[row];  C = h1 = A @ W1 + b1; accumulate col stats
// MODE 1: A = relu(h1 * scale[k] + shift[k]); C = x_out = relu(A @ W2 + b2)
// Buffers selected INSIDE the kernel (never host-passed device-symbol addrs).
#define TILE_BYTES (HD * BPAD * 2)          // 34816
#define S_AHI 0
#define S_ALO TILE_BYTES
#define S_BHI (2 * TILE_BYTES)
#define S_BLO (3 * TILE_BYTES)
#define SMEM_SZ (4 * TILE_BYTES)            // 139264

template <int MODE>
__global__ __launch_bounds__(256, 1)
void tgemm_kernel(const float* __restrict__ nc,
                  const float* __restrict__ bias,
                  int n, int sel, int slot) {
    extern __shared__ char smem[];
    uint32_t sb = smem_u32(smem);
    int tid = threadIdx.x, wid = tid >> 5, lane = tid & 31;
    int warp_m = wid & 3;                    // rows warp_m*32
    int warp_n = wid >> 2;                   // cols warp_n*64

    const float* Ain;
    float* Cout;
    if (MODE == 0) { Ain = sel ? g_xB : g_xA; Cout = g_h1; }
    else           { Ain = g_h1;              Cout = sel ? g_xB : g_xA; }

    // ---- copy pre-split W tiles ONCE per CTA (already padded image) ----
    {
        const uint4* wh = (const uint4*)g_Whi[slot];
        const uint4* wl = (const uint4*)g_Wlo[slot];
        uint4* dh = (uint4*)(smem + S_BHI);
        uint4* dl = (uint4*)(smem + S_BLO);
        for (int i = tid; i < TILE_BYTES / 16; i += 256) {
            dh[i] = wh[i];
            dl[i] = wl[i];
        }
    }

    // per-lane ldmatrix base offsets
    int lrow = lane & 15;
    int lblk = (lane >> 4) * 16;
    uint32_t aBase = sb + (warp_m * 32 + lrow) * (BPAD * 2) + lblk;
    uint32_t bBase = sb + lrow * (BPAD * 2) + (warp_n * 64) * 2 + lblk;

    int tiles = (n + 127) / 128;
    for (int t = blockIdx.x; t < tiles; t += gridDim.x) {
        int block_row = t * 128;

        // ---- fused A producer: load, fuse, bf16 hi/lo split ----
#pragma unroll 4
        for (int it = 0; it < 16; it++) {
            int f = tid + it * 256;              // 0..4095 float4 slots
            int row = f >> 5;                    // 0..127
            int kk = (f & 31) << 2;              // 0..124
            int grow = block_row + row;
            float4 v = make_float4(0.f, 0.f, 0.f, 0.f);
            if (grow < n) {
                v = *reinterpret_cast<const float4*>(Ain + (size_t)grow * HD + kk);
                if (MODE == 0) {
                    float w = __ldg(nc + grow);
                    float4 u = *reinterpret_cast<const float4*>(g_agg + (size_t)grow * HD + kk);
                    v.x = fmaf(u.x, w, v.x);
                    v.y = fmaf(u.y, w, v.y);
                    v.z = fmaf(u.z, w, v.z);
                    v.w = fmaf(u.w, w, v.w);
                } else {
                    float4 sc = *reinterpret_cast<const float4*>(g_scale + kk);
                    float4 sh = *reinterpret_cast<const float4*>(g_shift + kk);
                    v.x = fmaxf(fmaf(v.x, sc.x, sh.x), 0.f);
                    v.y = fmaxf(fmaf(v.y, sc.y, sh.y), 0.f);
                    v.z = fmaxf(fmaf(v.z, sc.z, sh.z), 0.f);
                    v.w = fmaxf(fmaf(v.w, sc.w, sh.w), 0.f);
                }
            }
            __nv_bfloat16 h0 = __float2bfloat16(v.x);
            __nv_bfloat16 h1 = __float2bfloat16(v.y);
            __nv_bfloat16 h2 = __float2bfloat16(v.z);
            __nv_bfloat16 h3 = __float2bfloat16(v.w);
            __nv_bfloat16 l0 = __float2bfloat16(v.x - __bfloat162float(h0));
            __nv_bfloat16 l1 = __float2bfloat16(v.y - __bfloat162float(h1));
            __nv_bfloat16 l2 = __float2bfloat16(v.z - __bfloat162float(h2));
            __nv_bfloat16 l3 = __float2bfloat16(v.w - __bfloat162float(h3));
            uint2 hp; hp.x = pack_bf(h0, h1); hp.y = pack_bf(h2, h3);
            uint2 lp; lp.x = pack_bf(l0, l1); lp.y = pack_bf(l2, l3);
            int off = row * (BPAD * 2) + kk * 2;     // bytes
            *(uint2*)(smem + S_AHI + off) = hp;
            *(uint2*)(smem + S_ALO + off) = lp;
        }
        __syncthreads();

        // ---- MMA mainloop: 8 k-steps, 3 products, fp32 accumulate ----
        float acc[2][8][4];
#pragma unroll
        for (int mf = 0; mf < 2; mf++)
#pragma unroll
            for (int nf = 0; nf < 8; nf++)
#pragma unroll
                for (int q = 0; q < 4; q++) acc[mf][nf][q] = 0.f;

#pragma unroll
        for (int ks = 0; ks < 8; ks++) {
            uint32_t ah[2][4], al[2][4], bh[8][2], bl[8][2];
#pragma unroll
            for (int mf = 0; mf < 2; mf++) {
                uint32_t addr = aBase + mf * 16 * (BPAD * 2) + ks * 32;
                ldmatrix_x4(ah[mf], addr + S_AHI);
                ldmatrix_x4(al[mf], addr + S_ALO);
            }
#pragma unroll
            for (int nb = 0; nb < 4; nb++) {
                uint32_t addr = bBase + ks * 16 * (BPAD * 2) + nb * 32;
                uint32_t rh[4], rl[4];
                ldmatrix_x4_trans(rh, addr + S_BHI);
                ldmatrix_x4_trans(rl, addr + S_BLO);
                bh[2 * nb][0] = rh[0]; bh[2 * nb][1] = rh[1];
                bh[2 * nb + 1][0] = rh[2]; bh[2 * nb + 1][1] = rh[3];
                bl[2 * nb][0] = rl[0]; bl[2 * nb][1] = rl[1];
                bl[2 * nb + 1][0] = rl[2]; bl[2 * nb + 1][1] = rl[3];
            }
#pragma unroll
            for (int mf = 0; mf < 2; mf++)
#pragma unroll
                for (int nf = 0; nf < 8; nf++) {
                    mma_bf16(acc[mf][nf], ah[mf], bh[nf]);
                    mma_bf16(acc[mf][nf], ah[mf], bl[nf]);
                    mma_bf16(acc[mf][nf], al[mf], bh[nf]);
                }
        }

        // ---- epilogue: bias, (stats | relu), direct fragment stores ----
        int r0 = block_row + warp_m * 32 + (lane >> 2);
#pragma unroll
        for (int nf = 0; nf < 8; nf++) {
            int col = warp_n * 64 + nf * 8 + (lane & 3) * 2;
            float b0 = __ldg(bias + col), b1 = __ldg(bias + col + 1);
            float v[4][2];
#pragma unroll
            for (int mf = 0; mf < 2; mf++) {
                v[mf * 2][0] = acc[mf][nf][0] + b0;
                v[mf * 2][1] = acc[mf][nf][1] + b1;
                v[mf * 2 + 1][0] = acc[mf][nf][2] + b0;
                v[mf * 2 + 1][1] = acc[mf][nf][3] + b1;
            }
            bool val[4];
            val[0] = r0 < n; val[1] = r0 + 8 < n; val[2] = r0 + 16 < n; val[3] = r0 + 24 < n;
            if (MODE == 0) {
                float s0 = 0.f, s1 = 0.f, q0 = 0.f, q1 = 0.f;
#pragma unroll
                for (int p = 0; p < 4; p++) {
                    if (val[p]) {
                        s0 += v[p][0]; q0 += v[p][0] * v[p][0];
                        s1 += v[p][1]; q1 += v[p][1] * v[p][1];
                    }
                }
#pragma unroll
                for (int d = 4; d < 32; d <<= 1) {
                    s0 += __shfl_xor_sync(0xFFFFFFFFu, s0, d);
                    s1 += __shfl_xor_sync(0xFFFFFFFFu, s1, d);
                    q0 += __shfl_xor_sync(0xFFFFFFFFu, q0, d);
                    q1 += __shfl_xor_sync(0xFFFFFFFFu, q1, d);
                }
                if (lane < 4) {
                    int c0 = warp_n * 64 + nf * 8 + lane * 2;
                    atomicAdd(&g_stats[c0], s0);
                    atomicAdd(&g_stats[c0 + 1], s1);
                    atomicAdd(&g_stats[HD + c0], q0);
                    atomicAdd(&g_stats[HD + c0 + 1], q1);
                }
            } else {
#pragma unroll
                for (int p = 0; p < 4; p++) {
                    v[p][0] = fmaxf(v[p][0], 0.f);
                    v[p][1] = fmaxf(v[p][1], 0.f);
                }
            }
#pragma unroll
            for (int p = 0; p < 4; p++) {
                int row = r0 + ((p & 1) ? 8 : 0) + ((p >> 1) ? 16 : 0);
                int pi = (p & 1) + (p >> 1) * 2;
                if (row < n) {
                    float2 o = make_float2(v[pi][0], v[pi][1]);
                    *reinterpret_cast<float2*>(Cout + (size_t)row * HD + col) = o;
                }
            }
        }
        __syncthreads();   // A/B SMEM reuse barrier before next tile's producer
    }
}

// ---------------- BN parameter computation (self-resetting stats) --------------
__global__ void bn_params_kernel(const float* __restrict__ gamma,
                                 const float* __restrict__ beta, int n) {
    int h = threadIdx.x;
    float invn = 1.f / (float)n;
    float mu = g_stats[h] * invn;
    float var = g_stats[HD + h] * invn - mu * mu;
    float s = gamma[h] * rsqrtf(var + 1e-5f);
    g_scale[h] = s;
    g_shift[h] = beta[h] - mu * s;
    g_stats[h] = 0.f;                 // reset for next layer's tgemm<0>
    g_stats[HD + h] = 0.f;
}

// ---------------- pooling ------------------------------------------------------
__global__ void pool_kernel(const void* __restrict__ batch, int n, int sel) {
    int i = blockIdx.x * (blockDim.x >> 5) + (threadIdx.x >> 5);
    if (i >= n) return;
    int lane = threadIdx.x & 31;
    int is64 = g_idx64;
    const float* x = sel ? g_xB : g_xA;
    long long g = load_index(batch, i, is64);
    float4 v = *reinterpret_cast<const float4*>(x + (size_t)i * HD + lane * 4);
    red_add_v4(g_pool + g * HD + lane * 4, v);
    if (lane == 0) atomicAdd(&g_cnt[g], 1.f);
}

// ---------------- classifier head ----------------------------------------------
__global__ void head_kernel(const float* __restrict__ Wc,
                            const float* __restrict__ bc,
                            float* __restrict__ out) {
    int g = blockIdx.x;
    int h = threadIdx.x;
    float cnt = g_cnt[g];
    float v = g_pool[g * HD + h] / fmaxf(cnt, 1.f);
    __shared__ float sh[HD];
    for (int c = 0; c < NCLS; c++) {
        sh[h] = v * Wc[h * NCLS + c];
        __syncthreads();
        for (int s = 64; s > 0; s >>= 1) {
            if (h < s) sh[h] += sh[h + s];
            __syncthreads();
        }
        if (h == 0) out[g * NCLS + c] = sh[0] + bc[c];
        __syncthreads();
    }
}

// ---------------- launch ---------------------------------------------------------
extern "C" void kernel_launch(void* const* d_in, const int* in_sizes, int n_in,
                              void* d_out, int out_size) {
    cudaFuncSetAttribute(tgemm_kernel<0>,
                         cudaFuncAttributeMaxDynamicSharedMemorySize, SMEM_SZ);
    cudaFuncSetAttribute(tgemm_kernel<1>,
                         cudaFuncAttributeMaxDynamicSharedMemorySize, SMEM_SZ);

    // Detect input ordering: signature order has edge_index (1.6M elems) at [1];
    // setup_inputs dict order has node_centrality (50K) at [1].
    int ix, iei, ib, inc_, iec, iw1, ib1, ig1, ibe1, iw2, ib2, iwc, ibc;
    ix = 0;
    if (n_in >= 13 && in_sizes[1] > 1000000) {
        iei = 1; ib = 2; inc_ = 3; iec = 4;
        iw1 = 5; ib1 = 6; ig1 = 7; ibe1 = 8;
        iw2 = 9; ib2 = 10; iwc = 11; ibc = 12;
    } else {
        inc_ = 1; iec = 2; iw1 = 3; ib1 = 4; ig1 = 5; ibe1 = 6;
        iw2 = 7; ib2 = 8; iwc = 9; ibc = 10; iei = 11; ib = 12;
    }

    const float* x   = (const float*)d_in[ix];
    const void*  ei  = d_in[iei];
    const void*  bat = d_in[ib];
    const float* nc  = (const float*)d_in[inc_];
    const float* ec  = (const float*)d_in[iec];
    const float* W1  = (const float*)d_in[iw1];
    const float* b1  = (const float*)d_in[ib1];
    const float* g1  = (const float*)d_in[ig1];
    const float* be1 = (const float*)d_in[ibe1];
    const float* W2  = (const float*)d_in[iw2];
    const float* b2  = (const float*)d_in[ib2];
    const float* Wc  = (const float*)d_in[iwc];
    const float* bc  = (const float*)d_in[ibc];
    float* out = (float*)d_out;

    int n = in_sizes[ix] / HD;
    int E = in_sizes[iei] / 2;
    int n4 = n * (HD / 4);
    bool use_csr = (E <= EMAX) && (n <= NMAX);

    detect_idx_kernel<<<1, 32>>>(ei, E, n);
    copy_x_kernel<<<512, 256>>>((const float4*)x, n4);
    conv_w_all_kernel<<<(6 * HD * HD + 255) / 256, 256>>>(W1, W2);

    int tiles = (n + 127) / 128;
    int gemm_grid = tiles < 148 ? tiles : 148;
    int pool_blocks = (n + 7) / 8;

    if (use_csr) {
        int nchunks = (n + 511) / 512;
        zero_deg_stats_kernel<<<(n + 256) / 256, 256>>>(n);
        hist_kernel<<<512, 256>>>(ei, E);
        scan1_kernel<<<nchunks, 512>>>(n);
        scan2_kernel<<<1, 512>>>(nchunks, E, n);
        scan3_kernel<<<(n + 255) / 256, 256>>>(n);
        scatter_kernel<<<512, 256>>>(ei, ec, E);
    }

    int agg_blocks = (n + 7) / 8;
    int edge_blocks = (E + EB - 1) / EB;

    for (int l = 0; l < 3; l++) {
        int sel_in = l & 1;        // l=0: in A, l=1: in B, l=2: in A
        int sel_out = sel_in ^ 1;
        if (use_csr) {
            csr_agg_kernel<<<agg_blocks, 256>>>(n, sel_in);
        } else {
            zero_agg_stats_kernel<<<2048, 256>>>(n4);
            edge_agg_kernel<<<edge_blocks, 256>>>(ei, ec, E, sel_in);
        }
        tgemm_kernel<0><<<gemm_grid, 256, SMEM_SZ>>>(nc, b1 + l * HD, n, sel_in, l);
        bn_params_kernel<<<1, HD>>>(g1 + l * HD, be1 + l * HD, n);
        tgemm_kernel<1><<<gemm_grid, 256, SMEM_SZ>>>(nullptr, b2 + l * HD, n, sel_out, 3 + l);
    }

    zero_pool_kernel<<<64, 256>>>();
    pool_kernel<<<pool_blocks, 256>>>(bat, n, 1);  // final activations live in g_xB
    head_kernel<<<NG, HD>>>(Wc, bc, out);
}

// round 9
// speedup vs baseline: 14.6615x; 1.0328x over previous
#include <cuda_runtime.h>
#include <cuda_bf16.h>
#include <cstdint>

#define NMAX 50000
#define EMAX 800000
#define HD 128
#define NG 128
#define NCLS 10
#define BPAD 136                      // padded row stride (bf16 elems), 272B: conflict-free ldmatrix
#define EB 128                        // edges staged per block (fallback path)

// ---------------- scratch (device globals; no runtime allocation) -----------
// NOTE: referenced ONLY from device code (selected via int selectors).
// Host-passed &g_x* resolves to host shadow memory (NVLink-C2C, 15-22x slow).
__device__ float g_xA[NMAX * HD];
__device__ float g_xB[NMAX * HD];
__device__ float g_agg[NMAX * HD];
__device__ float g_h1[NMAX * HD];
__device__ float g_stats[2 * HD];   // [0:128) col sums, [128:256) col sumsq
__device__ float g_scale[HD];
__device__ float g_shift[HD];
__device__ float g_pool[NG * HD];
__device__ float g_cnt[NG];
__device__ int   g_idx64;           // 1 if indices are int64, 0 if int32
// CSR of the (static) edge set, built once per call; (src, w) packed as int2
__device__ int   g_deg[NMAX + 1];
__device__ int   g_off[NMAX + 1];
__device__ int   g_cursor[NMAX];
__device__ int   g_bsum[128];
__device__ int2  g_csr[EMAX];
// pre-split weights in the padded SMEM image: [k][n], row stride BPAD
__device__ __nv_bfloat16 g_Whi[6][HD * BPAD];
__device__ __nv_bfloat16 g_Wlo[6][HD * BPAD];

// ---------------- helpers -----------------------------------------------------
__device__ __forceinline__ uint32_t smem_u32(const void* p) {
    uint32_t a;
    asm("{ .reg .u64 t; cvta.to.shared.u64 t, %1; cvt.u32.u64 %0, t; }"
        : "=r"(a) : "l"(p));
    return a;
}
__device__ __forceinline__ void red_add_v4(float* p, float4 v) {
    asm volatile("red.global.add.v4.f32 [%0], {%1,%2,%3,%4};"
                 :: "l"(p), "f"(v.x), "f"(v.y), "f"(v.z), "f"(v.w)
                 : "memory");
}
__device__ __forceinline__ uint32_t pack_bf(__nv_bfloat16 a, __nv_bfloat16 b) {
    uint16_t ua = *(uint16_t*)&a, ub = *(uint16_t*)&b;
    return (uint32_t)ua | ((uint32_t)ub << 16);
}
__device__ __forceinline__ void ldmatrix_x4(uint32_t* r, uint32_t addr) {
    asm volatile("ldmatrix.sync.aligned.m8n8.x4.shared.b16 {%0,%1,%2,%3}, [%4];"
                 : "=r"(r[0]), "=r"(r[1]), "=r"(r[2]), "=r"(r[3]) : "r"(addr));
}
__device__ __forceinline__ void ldmatrix_x4_trans(uint32_t* r, uint32_t addr) {
    asm volatile("ldmatrix.sync.aligned.m8n8.x4.trans.shared.b16 {%0,%1,%2,%3}, [%4];"
                 : "=r"(r[0]), "=r"(r[1]), "=r"(r[2]), "=r"(r[3]) : "r"(addr));
}
__device__ __forceinline__ void mma_bf16(float* c, const uint32_t* a, const uint32_t* b) {
    asm volatile(
        "mma.sync.aligned.m16n8k16.row.col.f32.bf16.bf16.f32 "
        "{%0,%1,%2,%3}, {%4,%5,%6,%7}, {%8,%9}, {%0,%1,%2,%3};"
        : "+f"(c[0]), "+f"(c[1]), "+f"(c[2]), "+f"(c[3])
        : "r"(a[0]), "r"(a[1]), "r"(a[2]), "r"(a[3]), "r"(b[0]), "r"(b[1]));
}

// ---------------- index dtype detect ------------------------------------------
__global__ void detect_idx_kernel(const void* ei, int E, int n) {
    if (threadIdx.x != 0 || blockIdx.x != 0) return;
    const long long* p64 = (const long long*)ei;
    int ok64 = 1;
    for (int i = 0; i < 16; i++) {
        long long v = p64[i];
        if (v < 0 || v >= (long long)n) { ok64 = 0; break; }
    }
    if (ok64) {
        for (int i = 0; i < 16; i++) {
            long long v = p64[(size_t)E + i];
            if (v < 0 || v >= (long long)n) { ok64 = 0; break; }
        }
    }
    g_idx64 = ok64;
}
__device__ __forceinline__ long long load_index(const void* base, long long off, int is64) {
    if (is64) return ((const long long*)base)[off];
    return (long long)((const int*)base)[off];
}

// ---------------- small utility kernels --------------------------------------
__global__ void copy_x_kernel(const float4* __restrict__ src, int n4) {
    float4* dst = reinterpret_cast<float4*>(g_xA);
    for (int i = blockIdx.x * blockDim.x + threadIdx.x; i < n4;
         i += gridDim.x * blockDim.x)
        dst[i] = src[i];
}
__global__ void zero_deg_stats_kernel(int n) {
    int i = blockIdx.x * blockDim.x + threadIdx.x;
    if (i <= n) g_deg[i] = 0;
    if (i < 2 * HD) g_stats[i] = 0.f;
}
__global__ void zero_pool_kernel() {
    int i = blockIdx.x * blockDim.x + threadIdx.x;
    if (i < NG * HD) g_pool[i] = 0.f;
    if (i < NG) g_cnt[i] = 0.f;
}
__global__ void zero_agg_stats_kernel(int n4) {   // fallback path only
    int i = blockIdx.x * blockDim.x + threadIdx.x;
    if (i < 2 * HD) g_stats[i] = 0.f;
    float4 z = make_float4(0.f, 0.f, 0.f, 0.f);
    float4* a = reinterpret_cast<float4*>(g_agg);
    for (int j = i; j < n4; j += gridDim.x * blockDim.x) a[j] = z;
}

// ---------------- weight pre-split (all 6 slots in one launch) -----------------
__global__ void conv_w_all_kernel(const float* __restrict__ W1,
                                  const float* __restrict__ W2) {
    int i = blockIdx.x * blockDim.x + threadIdx.x;
    if (i >= 6 * HD * HD) return;
    int slot = i >> 14;
    int j = i & (HD * HD - 1);
    int n = j & 127, k = j >> 7;
    const float* W = (slot < 3) ? (W1 + (size_t)slot * HD * HD)
                                : (W2 + (size_t)(slot - 3) * HD * HD);
    float w = W[k * HD + n];
    __nv_bfloat16 hi = __float2bfloat16(w);
    float lof = w - __bfloat162float(hi);
    g_Whi[slot][k * BPAD + n] = hi;
    g_Wlo[slot][k * BPAD + n] = __float2bfloat16(lof);
}

// ---------------- CSR construction (once per call) -----------------------------
__global__ void hist_kernel(const void* __restrict__ ei, int E) {
    int is64 = g_idx64;
    for (long long e = blockIdx.x * blockDim.x + threadIdx.x; e < E;
         e += (long long)gridDim.x * blockDim.x) {
        int d = (int)load_index(ei, (long long)E + e, is64);
        atomicAdd(&g_deg[d], 1);
    }
}
__global__ void scan1_kernel(int n) {
    __shared__ int sh[512];
    int t = threadIdx.x;
    int i = blockIdx.x * 512 + t;
    int v = (i < n) ? g_deg[i] : 0;
    sh[t] = v;
    __syncthreads();
#pragma unroll
    for (int o = 1; o < 512; o <<= 1) {
        int tmp = (t >= o) ? sh[t - o] : 0;
        __syncthreads();
        sh[t] += tmp;
        __syncthreads();
    }
    if (i < n) g_off[i] = sh[t] - v;        // exclusive within chunk
    if (t == 511) g_bsum[blockIdx.x] = sh[511];
}
__global__ void scan2_kernel(int nchunks, int E, int n) {
    __shared__ int sh[512];
    int t = threadIdx.x;
    int v = (t < nchunks) ? g_bsum[t] : 0;
    sh[t] = v;
    __syncthreads();
#pragma unroll
    for (int o = 1; o < 512; o <<= 1) {
        int tmp = (t >= o) ? sh[t - o] : 0;
        __syncthreads();
        sh[t] += tmp;
        __syncthreads();
    }
    if (t < nchunks) g_bsum[t] = sh[t] - v; // exclusive chunk offsets
    if (t == 0) g_off[n] = E;
}
__global__ void scan3_kernel(int n) {
    int i = blockIdx.x * blockDim.x + threadIdx.x;
    if (i < n) {
        int o = g_off[i] + g_bsum[i >> 9];
        g_off[i] = o;
        g_cursor[i] = o;
    }
}
__global__ void scatter_kernel(const void* __restrict__ ei,
                               const float* __restrict__ ec, int E) {
    int is64 = g_idx64;
    for (long long e = blockIdx.x * blockDim.x + threadIdx.x; e < E;
         e += (long long)gridDim.x * blockDim.x) {
        int s = (int)load_index(ei, e, is64);
        int d = (int)load_index(ei, (long long)E + e, is64);
        float w = __ldg(ec + e);
        int pos = atomicAdd(&g_cursor[d], 1);
        g_csr[pos] = make_int2(s, __float_as_int(w));
    }
}

// ---------------- CSR aggregation: agg[v] = sum_j x[src_j] * w_j ---------------
// Warp per node; 4-wide batched gathers for MLP; one 512B store per node.
__global__ __launch_bounds__(256, 4)
void csr_agg_kernel(int n, int sel) {
    int v = blockIdx.x * 8 + (threadIdx.x >> 5);
    if (v >= n) return;
    int lane = threadIdx.x & 31;
    const float* x = sel ? g_xB : g_xA;
    int j = g_off[v], end = g_off[v + 1];
    float4 acc = make_float4(0.f, 0.f, 0.f, 0.f);

    for (; j + 4 <= end; j += 4) {
        int2 e0 = __ldg(g_csr + j);
        int2 e1 = __ldg(g_csr + j + 1);
        int2 e2 = __ldg(g_csr + j + 2);
        int2 e3 = __ldg(g_csr + j + 3);
        float w0 = __int_as_float(e0.y);
        float w1 = __int_as_float(e1.y);
        float w2 = __int_as_float(e2.y);
        float w3 = __int_as_float(e3.y);
        float4 v0 = *reinterpret_cast<const float4*>(x + (size_t)e0.x * HD + lane * 4);
        float4 v1 = *reinterpret_cast<const float4*>(x + (size_t)e1.x * HD + lane * 4);
        float4 v2 = *reinterpret_cast<const float4*>(x + (size_t)e2.x * HD + lane * 4);
        float4 v3 = *reinterpret_cast<const float4*>(x + (size_t)e3.x * HD + lane * 4);
        acc.x = fmaf(v0.x, w0, acc.x); acc.y = fmaf(v0.y, w0, acc.y);
        acc.z = fmaf(v0.z, w0, acc.z); acc.w = fmaf(v0.w, w0, acc.w);
        acc.x = fmaf(v1.x, w1, acc.x); acc.y = fmaf(v1.y, w1, acc.y);
        acc.z = fmaf(v1.z, w1, acc.z); acc.w = fmaf(v1.w, w1, acc.w);
        acc.x = fmaf(v2.x, w2, acc.x); acc.y = fmaf(v2.y, w2, acc.y);
        acc.z = fmaf(v2.z, w2, acc.z); acc.w = fmaf(v2.w, w2, acc.w);
        acc.x = fmaf(v3.x, w3, acc.x); acc.y = fmaf(v3.y, w3, acc.y);
        acc.z = fmaf(v3.z, w3, acc.z); acc.w = fmaf(v3.w, w3, acc.w);
    }
    for (; j < end; j++) {
        int2 e = __ldg(g_csr + j);
        float w = __int_as_float(e.y);
        float4 vv = *reinterpret_cast<const float4*>(x + (size_t)e.x * HD + lane * 4);
        acc.x = fmaf(vv.x, w, acc.x); acc.y = fmaf(vv.y, w, acc.y);
        acc.z = fmaf(vv.z, w, acc.z); acc.w = fmaf(vv.w, w, acc.w);
    }
    *reinterpret_cast<float4*>(g_agg + (size_t)v * HD + lane * 4) = acc;
}

// ---------------- fallback edge aggregation (atomic path, E > EMAX) ------------
__global__ __launch_bounds__(256, 4)
void edge_agg_kernel(const void* __restrict__ ei,
                     const float* __restrict__ ec,
                     int E, int sel) {
    __shared__ int s_src[EB];
    __shared__ int s_dst[EB];
    __shared__ float s_w[EB];
    int tid = threadIdx.x, wid = tid >> 5, lane = tid & 31;
    int is64 = g_idx64;
    const float* x = sel ? g_xB : g_xA;

    long long base = (long long)blockIdx.x * EB;
    if (base >= E) return;
    int cnt = min(EB, (int)(E - base));
    if (tid < cnt) {
        s_src[tid] = (int)load_index(ei, base + tid, is64);
        s_dst[tid] = (int)load_index(ei, (long long)E + base + tid, is64);
        s_w[tid] = __ldg(ec + base + tid);
    }
    __syncthreads();

    int e = wid;
    if (e < cnt) {
        int s = s_src[e];
        float4 v = *reinterpret_cast<const float4*>(x + (size_t)s * HD + lane * 4);
        while (true) {
            int en = e + 8;
            float4 vn;
            if (en < cnt) {
                int sn = s_src[en];
                vn = *reinterpret_cast<const float4*>(x + (size_t)sn * HD + lane * 4);
            }
            float w = s_w[e];
            int d = s_dst[e];
            float4 o = make_float4(v.x * w, v.y * w, v.z * w, v.w * w);
            red_add_v4(g_agg + (size_t)d * HD + lane * 4, o);
            if (en >= cnt) break;
            v = vn; e = en;
        }
    }
}

// ---------------- tensor-core bf16x3 fused GEMM (persistent, 64-row tiles) -----
// 2 CTAs/SM: one CTA's A-producer overlaps the co-resident CTA's MMA loop.
// MODE 0: A = x_in + agg * nc[row];  C = h1 = A @ W1 + b1; accumulate col stats
// MODE 1: A = relu(h1 * scale[k] + shift[k]); C = x_out = relu(A @ W2 + b2)
#define TM 64                                // tile rows
#define TILE_A_BYTES (TM * BPAD * 2)         // 17408
#define TILE_B_BYTES (HD * BPAD * 2)         // 34816
#define S_AHI 0
#define S_ALO TILE_A_BYTES
#define S_BHI (2 * TILE_A_BYTES)
#define S_BLO (2 * TILE_A_BYTES + TILE_B_BYTES)
#define SMEM_SZ (2 * TILE_A_BYTES + 2 * TILE_B_BYTES)   // 104448

template <int MODE>
__global__ __launch_bounds__(256, 2)
void tgemm_kernel(const float* __restrict__ nc,
                  const float* __restrict__ bias,
                  int n, int sel, int slot) {
    extern __shared__ char smem[];
    uint32_t sb = smem_u32(smem);
    int tid = threadIdx.x, wid = tid >> 5, lane = tid & 31;
    int warp_m = wid & 1;                    // rows warp_m*32
    int warp_n = wid >> 1;                   // cols warp_n*32

    const float* Ain;
    float* Cout;
    if (MODE == 0) { Ain = sel ? g_xB : g_xA; Cout = g_h1; }
    else           { Ain = g_h1;              Cout = sel ? g_xB : g_xA; }

    // ---- copy pre-split W tiles ONCE per CTA (already padded image) ----
    {
        const uint4* wh = (const uint4*)g_Whi[slot];
        const uint4* wl = (const uint4*)g_Wlo[slot];
        uint4* dh = (uint4*)(smem + S_BHI);
        uint4* dl = (uint4*)(smem + S_BLO);
        for (int i = tid; i < TILE_B_BYTES / 16; i += 256) {
            dh[i] = wh[i];
            dl[i] = wl[i];
        }
    }

    // per-lane ldmatrix base offsets
    int lrow = lane & 15;
    int lblk = (lane >> 4) * 16;
    uint32_t aBase = sb + (warp_m * 32 + lrow) * (BPAD * 2) + lblk;
    uint32_t bBase = sb + lrow * (BPAD * 2) + (warp_n * 32) * 2 + lblk;

    int tiles = (n + TM - 1) / TM;
    for (int t = blockIdx.x; t < tiles; t += gridDim.x) {
        int block_row = t * TM;

        // ---- fused A producer: load, fuse, bf16 hi/lo split ----
#pragma unroll 4
        for (int it = 0; it < 8; it++) {
            int f = tid + it * 256;              // 0..2047 float4 slots
            int row = f >> 5;                    // 0..63
            int kk = (f & 31) << 2;              // 0..124
            int grow = block_row + row;
            float4 v = make_float4(0.f, 0.f, 0.f, 0.f);
            if (grow < n) {
                v = *reinterpret_cast<const float4*>(Ain + (size_t)grow * HD + kk);
                if (MODE == 0) {
                    float w = __ldg(nc + grow);
                    float4 u = *reinterpret_cast<const float4*>(g_agg + (size_t)grow * HD + kk);
                    v.x = fmaf(u.x, w, v.x);
                    v.y = fmaf(u.y, w, v.y);
                    v.z = fmaf(u.z, w, v.z);
                    v.w = fmaf(u.w, w, v.w);
                } else {
                    float4 sc = *reinterpret_cast<const float4*>(g_scale + kk);
                    float4 sh = *reinterpret_cast<const float4*>(g_shift + kk);
                    v.x = fmaxf(fmaf(v.x, sc.x, sh.x), 0.f);
                    v.y = fmaxf(fmaf(v.y, sc.y, sh.y), 0.f);
                    v.z = fmaxf(fmaf(v.z, sc.z, sh.z), 0.f);
                    v.w = fmaxf(fmaf(v.w, sc.w, sh.w), 0.f);
                }
            }
            __nv_bfloat16 h0 = __float2bfloat16(v.x);
            __nv_bfloat16 h1 = __float2bfloat16(v.y);
            __nv_bfloat16 h2 = __float2bfloat16(v.z);
            __nv_bfloat16 h3 = __float2bfloat16(v.w);
            __nv_bfloat16 l0 = __float2bfloat16(v.x - __bfloat162float(h0));
            __nv_bfloat16 l1 = __float2bfloat16(v.y - __bfloat162float(h1));
            __nv_bfloat16 l2 = __float2bfloat16(v.z - __bfloat162float(h2));
            __nv_bfloat16 l3 = __float2bfloat16(v.w - __bfloat162float(h3));
            uint2 hp; hp.x = pack_bf(h0, h1); hp.y = pack_bf(h2, h3);
            uint2 lp; lp.x = pack_bf(l0, l1); lp.y = pack_bf(l2, l3);
            int off = row * (BPAD * 2) + kk * 2;     // bytes
            *(uint2*)(smem + S_AHI + off) = hp;
            *(uint2*)(smem + S_ALO + off) = lp;
        }
        __syncthreads();

        // ---- MMA mainloop: 8 k-steps, 3 products, fp32 accumulate ----
        float acc[2][4][4];
#pragma unroll
        for (int mf = 0; mf < 2; mf++)
#pragma unroll
            for (int nf = 0; nf < 4; nf++)
#pragma unroll
                for (int q = 0; q < 4; q++) acc[mf][nf][q] = 0.f;

#pragma unroll
        for (int ks = 0; ks < 8; ks++) {
            uint32_t ah[2][4], al[2][4], bh[4][2], bl[4][2];
#pragma unroll
            for (int mf = 0; mf < 2; mf++) {
                uint32_t addr = aBase + mf * 16 * (BPAD * 2) + ks * 32;
                ldmatrix_x4(ah[mf], addr + S_AHI);
                ldmatrix_x4(al[mf], addr + S_ALO);
            }
#pragma unroll
            for (int nb = 0; nb < 2; nb++) {
                uint32_t addr = bBase + ks * 16 * (BPAD * 2) + nb * 32;
                uint32_t rh[4], rl[4];
                ldmatrix_x4_trans(rh, addr + S_BHI);
                ldmatrix_x4_trans(rl, addr + S_BLO);
                bh[2 * nb][0] = rh[0]; bh[2 * nb][1] = rh[1];
                bh[2 * nb + 1][0] = rh[2]; bh[2 * nb + 1][1] = rh[3];
                bl[2 * nb][0] = rl[0]; bl[2 * nb][1] = rl[1];
                bl[2 * nb + 1][0] = rl[2]; bl[2 * nb + 1][1] = rl[3];
            }
#pragma unroll
            for (int mf = 0; mf < 2; mf++)
#pragma unroll
                for (int nf = 0; nf < 4; nf++) {
                    mma_bf16(acc[mf][nf], ah[mf], bh[nf]);
                    mma_bf16(acc[mf][nf], ah[mf], bl[nf]);
                    mma_bf16(acc[mf][nf], al[mf], bh[nf]);
                }
        }

        // ---- epilogue: bias, (stats | relu), direct fragment stores ----
        int r0 = block_row + warp_m * 32 + (lane >> 2);
#pragma unroll
        for (int nf = 0; nf < 4; nf++) {
            int col = warp_n * 32 + nf * 8 + (lane & 3) * 2;
            float b0 = __ldg(bias + col), b1 = __ldg(bias + col + 1);
            float v[4][2];
#pragma unroll
            for (int mf = 0; mf < 2; mf++) {
                v[mf * 2][0] = acc[mf][nf][0] + b0;
                v[mf * 2][1] = acc[mf][nf][1] + b1;
                v[mf * 2 + 1][0] = acc[mf][nf][2] + b0;
                v[mf * 2 + 1][1] = acc[mf][nf][3] + b1;
            }
            bool val[4];
            val[0] = r0 < n; val[1] = r0 + 8 < n; val[2] = r0 + 16 < n; val[3] = r0 + 24 < n;
            if (MODE == 0) {
                float s0 = 0.f, s1 = 0.f, q0 = 0.f, q1 = 0.f;
#pragma unroll
                for (int p = 0; p < 4; p++) {
                    if (val[p]) {
                        s0 += v[p][0]; q0 += v[p][0] * v[p][0];
                        s1 += v[p][1]; q1 += v[p][1] * v[p][1];
                    }
                }
#pragma unroll
                for (int d = 4; d < 32; d <<= 1) {
                    s0 += __shfl_xor_sync(0xFFFFFFFFu, s0, d);
                    s1 += __shfl_xor_sync(0xFFFFFFFFu, s1, d);
                    q0 += __shfl_xor_sync(0xFFFFFFFFu, q0, d);
                    q1 += __shfl_xor_sync(0xFFFFFFFFu, q1, d);
                }
                if (lane < 4) {
                    int c0 = warp_n * 32 + nf * 8 + lane * 2;
                    atomicAdd(&g_stats[c0], s0);
                    atomicAdd(&g_stats[c0 + 1], s1);
                    atomicAdd(&g_stats[HD + c0], q0);
                    atomicAdd(&g_stats[HD + c0 + 1], q1);
                }
            } else {
#pragma unroll
                for (int p = 0; p < 4; p++) {
                    v[p][0] = fmaxf(v[p][0], 0.f);
                    v[p][1] = fmaxf(v[p][1], 0.f);
                }
            }
#pragma unroll
            for (int p = 0; p < 4; p++) {
                int row = r0 + ((p & 1) ? 8 : 0) + ((p >> 1) ? 16 : 0);
                int pi = (p & 1) + (p >> 1) * 2;
                if (row < n) {
                    float2 o = make_float2(v[pi][0], v[pi][1]);
                    *reinterpret_cast<float2*>(Cout + (size_t)row * HD + col) = o;
                }
            }
        }
        __syncthreads();   // A SMEM reuse barrier before next tile's producer
    }
}

// ---------------- BN parameter computation (self-resetting stats) --------------
__global__ void bn_params_kernel(const float* __restrict__ gamma,
                                 const float* __restrict__ beta, int n) {
    int h = threadIdx.x;
    float invn = 1.f / (float)n;
    float mu = g_stats[h] * invn;
    float var = g_stats[HD + h] * invn - mu * mu;
    float s = gamma[h] * rsqrtf(var + 1e-5f);
    g_scale[h] = s;
    g_shift[h] = beta[h] - mu * s;
    g_stats[h] = 0.f;                 // reset for next layer's tgemm<0>
    g_stats[HD + h] = 0.f;
}

// ---------------- pooling ------------------------------------------------------
__global__ void pool_kernel(const void* __restrict__ batch, int n, int sel) {
    int i = blockIdx.x * (blockDim.x >> 5) + (threadIdx.x >> 5);
    if (i >= n) return;
    int lane = threadIdx.x & 31;
    int is64 = g_idx64;
    const float* x = sel ? g_xB : g_xA;
    long long g = load_index(batch, i, is64);
    float4 v = *reinterpret_cast<const float4*>(x + (size_t)i * HD + lane * 4);
    red_add_v4(g_pool + g * HD + lane * 4, v);
    if (lane == 0) atomicAdd(&g_cnt[g], 1.f);
}

// ---------------- classifier head ----------------------------------------------
__global__ void head_kernel(const float* __restrict__ Wc,
                            const float* __restrict__ bc,
                            float* __restrict__ out) {
    int g = blockIdx.x;
    int h = threadIdx.x;
    float cnt = g_cnt[g];
    float v = g_pool[g * HD + h] / fmaxf(cnt, 1.f);
    __shared__ float sh[HD];
    for (int c = 0; c < NCLS; c++) {
        sh[h] = v * Wc[h * NCLS + c];
        __syncthreads();
        for (int s = 64; s > 0; s >>= 1) {
            if (h < s) sh[h] += sh[h + s];
            __syncthreads();
        }
        if (h == 0) out[g * NCLS + c] = sh[0] + bc[c];
        __syncthreads();
    }
}

// ---------------- launch ---------------------------------------------------------
extern "C" void kernel_launch(void* const* d_in, const int* in_sizes, int n_in,
                              void* d_out, int out_size) {
    cudaFuncSetAttribute(tgemm_kernel<0>,
                         cudaFuncAttributeMaxDynamicSharedMemorySize, SMEM_SZ);
    cudaFuncSetAttribute(tgemm_kernel<1>,
                         cudaFuncAttributeMaxDynamicSharedMemorySize, SMEM_SZ);

    // Detect input ordering: signature order has edge_index (1.6M elems) at [1];
    // setup_inputs dict order has node_centrality (50K) at [1].
    int ix, iei, ib, inc_, iec, iw1, ib1, ig1, ibe1, iw2, ib2, iwc, ibc;
    ix = 0;
    if (n_in >= 13 && in_sizes[1] > 1000000) {
        iei = 1; ib = 2; inc_ = 3; iec = 4;
        iw1 = 5; ib1 = 6; ig1 = 7; ibe1 = 8;
        iw2 = 9; ib2 = 10; iwc = 11; ibc = 12;
    } else {
        inc_ = 1; iec = 2; iw1 = 3; ib1 = 4; ig1 = 5; ibe1 = 6;
        iw2 = 7; ib2 = 8; iwc = 9; ibc = 10; iei = 11; ib = 12;
    }

    const float* x   = (const float*)d_in[ix];
    const void*  ei  = d_in[iei];
    const void*  bat = d_in[ib];
    const float* nc  = (const float*)d_in[inc_];
    const float* ec  = (const float*)d_in[iec];
    const float* W1  = (const float*)d_in[iw1];
    const float* b1  = (const float*)d_in[ib1];
    const float* g1  = (const float*)d_in[ig1];
    const float* be1 = (const float*)d_in[ibe1];
    const float* W2  = (const float*)d_in[iw2];
    const float* b2  = (const float*)d_in[ib2];
    const float* Wc  = (const float*)d_in[iwc];
    const float* bc  = (const float*)d_in[ibc];
    float* out = (float*)d_out;

    int n = in_sizes[ix] / HD;
    int E = in_sizes[iei] / 2;
    int n4 = n * (HD / 4);
    bool use_csr = (E <= EMAX) && (n <= NMAX);

    detect_idx_kernel<<<1, 32>>>(ei, E, n);
    copy_x_kernel<<<512, 256>>>((const float4*)x, n4);
    conv_w_all_kernel<<<(6 * HD * HD + 255) / 256, 256>>>(W1, W2);

    int tiles = (n + TM - 1) / TM;
    int gemm_grid = tiles < 296 ? tiles : 296;
    int pool_blocks = (n + 7) / 8;

    if (use_csr) {
        int nchunks = (n + 511) / 512;
        zero_deg_stats_kernel<<<(n + 256) / 256, 256>>>(n);
        hist_kernel<<<512, 256>>>(ei, E);
        scan1_kernel<<<nchunks, 512>>>(n);
        scan2_kernel<<<1, 512>>>(nchunks, E, n);
        scan3_kernel<<<(n + 255) / 256, 256>>>(n);
        scatter_kernel<<<512, 256>>>(ei, ec, E);
    }

    int agg_blocks = (n + 7) / 8;
    int edge_blocks = (E + EB - 1) / EB;

    for (int l = 0; l < 3; l++) {
        int sel_in = l & 1;        // l=0: in A, l=1: in B, l=2: in A
        int sel_out = sel_in ^ 1;
        if (use_csr) {
            csr_agg_kernel<<<agg_blocks, 256>>>(n, sel_in);
        } else {
            zero_agg_stats_kernel<<<2048, 256>>>(n4);
            edge_agg_kernel<<<edge_blocks, 256>>>(ei, ec, E, sel_in);
        }
        tgemm_kernel<0><<<gemm_grid, 256, SMEM_SZ>>>(nc, b1 + l * HD, n, sel_in, l);
        bn_params_kernel<<<1, HD>>>(g1 + l * HD, be1 + l * HD, n);
        tgemm_kernel<1><<<gemm_grid, 256, SMEM_SZ>>>(nullptr, b2 + l * HD, n, sel_out, 3 + l);
    }

    zero_pool_kernel<<<64, 256>>>();
    pool_kernel<<<pool_blocks, 256>>>(bat, n, 1);  // final activations live in g_xB
    head_kernel<<<NG, HD>>>(Wc, bc, out);
}

// round 10
// speedup vs baseline: 16.7996x; 1.1458x over previous
#include <cuda_runtime.h>
#include <cuda_bf16.h>
#include <cstdint>

#define NMAX 50000
#define EMAX 800000
#define HD 128
#define NG 128
#define NCLS 10
#define BPAD 136                      // padded row stride (bf16 elems), 272B: conflict-free ldmatrix
#define EB 128                        // edges staged per block (fallback path)

// ---------------- scratch (device globals; no runtime allocation) -----------
// NOTE: referenced ONLY from device code (selected via int selectors).
// Host-passed &g_x* resolves to host shadow memory (NVLink-C2C, 15-22x slow).
// Harness pointers (d_in[i]) are true device pointers and safe as kernel args.
__device__ float g_xA[NMAX * HD];
__device__ float g_xB[NMAX * HD];
__device__ float g_agg[NMAX * HD];
__device__ float g_h1[NMAX * HD];
__device__ float g_stats[2 * HD];   // [0:128) col sums, [128:256) col sumsq
__device__ float g_scale[HD];
__device__ float g_shift[HD];
__device__ float g_pool[NG * HD];
__device__ float g_cnt[NG];
__device__ int   g_idx64;           // 1 if indices are int64, 0 if int32
// CSR of the (static) edge set, built once per call; (src, w) packed as int2
__device__ int   g_deg[NMAX + 1];
__device__ int   g_off[NMAX + 1];
__device__ int   g_cursor[NMAX];
__device__ int   g_bsum[128];
__device__ int2  g_csr[EMAX];
// pre-split weights in the padded SMEM image: [k][n], row stride BPAD
__device__ __nv_bfloat16 g_Whi[6][HD * BPAD];
__device__ __nv_bfloat16 g_Wlo[6][HD * BPAD];

// ---------------- helpers -----------------------------------------------------
__device__ __forceinline__ uint32_t smem_u32(const void* p) {
    uint32_t a;
    asm("{ .reg .u64 t; cvta.to.shared.u64 t, %1; cvt.u32.u64 %0, t; }"
        : "=r"(a) : "l"(p));
    return a;
}
__device__ __forceinline__ void red_add_v4(float* p, float4 v) {
    asm volatile("red.global.add.v4.f32 [%0], {%1,%2,%3,%4};"
                 :: "l"(p), "f"(v.x), "f"(v.y), "f"(v.z), "f"(v.w)
                 : "memory");
}
__device__ __forceinline__ uint32_t pack_bf(__nv_bfloat16 a, __nv_bfloat16 b) {
    uint16_t ua = *(uint16_t*)&a, ub = *(uint16_t*)&b;
    return (uint32_t)ua | ((uint32_t)ub << 16);
}
__device__ __forceinline__ void ldmatrix_x4(uint32_t* r, uint32_t addr) {
    asm volatile("ldmatrix.sync.aligned.m8n8.x4.shared.b16 {%0,%1,%2,%3}, [%4];"
                 : "=r"(r[0]), "=r"(r[1]), "=r"(r[2]), "=r"(r[3]) : "r"(addr));
}
__device__ __forceinline__ void ldmatrix_x4_trans(uint32_t* r, uint32_t addr) {
    asm volatile("ldmatrix.sync.aligned.m8n8.x4.trans.shared.b16 {%0,%1,%2,%3}, [%4];"
                 : "=r"(r[0]), "=r"(r[1]), "=r"(r[2]), "=r"(r[3]) : "r"(addr));
}
__device__ __forceinline__ void mma_bf16(float* c, const uint32_t* a, const uint32_t* b) {
    asm volatile(
        "mma.sync.aligned.m16n8k16.row.col.f32.bf16.bf16.f32 "
        "{%0,%1,%2,%3}, {%4,%5,%6,%7}, {%8,%9}, {%0,%1,%2,%3};"
        : "+f"(c[0]), "+f"(c[1]), "+f"(c[2]), "+f"(c[3])
        : "r"(a[0]), "r"(a[1]), "r"(a[2]), "r"(a[3]), "r"(b[0]), "r"(b[1]));
}
__device__ __forceinline__ long long load_index(const void* base, long long off, int is64) {
    if (is64) return ((const long long*)base)[off];
    return (long long)((const int*)base)[off];
}
// layer input select: sel<0 -> external harness pointer, 0 -> g_xA, 1 -> g_xB
__device__ __forceinline__ const float* pick_x(int sel, const float* xext) {
    if (sel < 0) return xext;
    return sel ? g_xB : g_xA;
}

// ---------------- small utility kernels --------------------------------------
__global__ void zero_deg_stats_pool_kernel(int n) {
    int i = blockIdx.x * blockDim.x + threadIdx.x;
    if (i <= n) g_deg[i] = 0;
    if (i < 2 * HD) g_stats[i] = 0.f;
    if (i < NG * HD) g_pool[i] = 0.f;
    if (i < NG) g_cnt[i] = 0.f;
}
__global__ void zero_agg_stats_kernel(int n4) {   // fallback path only
    int i = blockIdx.x * blockDim.x + threadIdx.x;
    if (i < 2 * HD) g_stats[i] = 0.f;
    float4 z = make_float4(0.f, 0.f, 0.f, 0.f);
    float4* a = reinterpret_cast<float4*>(g_agg);
    for (int j = i; j < n4; j += gridDim.x * blockDim.x) a[j] = z;
}

// ---------------- weight pre-split + idx-dtype detect (one launch) -------------
__global__ void conv_w_all_kernel(const float* __restrict__ W1,
                                  const float* __restrict__ W2,
                                  const void* __restrict__ ei, int E, int n_nodes) {
    int i = blockIdx.x * blockDim.x + threadIdx.x;
    if (i == 0) {           // fold index-dtype detection into this launch
        const long long* p64 = (const long long*)ei;
        int ok64 = 1;
        for (int t = 0; t < 16; t++) {
            long long v = p64[t];
            if (v < 0 || v >= (long long)n_nodes) { ok64 = 0; break; }
        }
        if (ok64) {
            for (int t = 0; t < 16; t++) {
                long long v = p64[(size_t)E + t];
                if (v < 0 || v >= (long long)n_nodes) { ok64 = 0; break; }
            }
        }
        g_idx64 = ok64;
    }
    if (i >= 6 * HD * HD) return;
    int slot = i >> 14;
    int j = i & (HD * HD - 1);
    int n = j & 127, k = j >> 7;
    const float* W = (slot < 3) ? (W1 + (size_t)slot * HD * HD)
                                : (W2 + (size_t)(slot - 3) * HD * HD);
    float w = W[k * HD + n];
    __nv_bfloat16 hi = __float2bfloat16(w);
    float lof = w - __bfloat162float(hi);
    g_Whi[slot][k * BPAD + n] = hi;
    g_Wlo[slot][k * BPAD + n] = __float2bfloat16(lof);
}

// ---------------- CSR construction (once per call) -----------------------------
__global__ void hist_kernel(const void* __restrict__ ei, int E) {
    int is64 = g_idx64;
    for (long long e = blockIdx.x * blockDim.x + threadIdx.x; e < E;
         e += (long long)gridDim.x * blockDim.x) {
        int d = (int)load_index(ei, (long long)E + e, is64);
        atomicAdd(&g_deg[d], 1);
    }
}
__global__ void scan1_kernel(int n) {
    __shared__ int sh[512];
    int t = threadIdx.x;
    int i = blockIdx.x * 512 + t;
    int v = (i < n) ? g_deg[i] : 0;
    sh[t] = v;
    __syncthreads();
#pragma unroll
    for (int o = 1; o < 512; o <<= 1) {
        int tmp = (t >= o) ? sh[t - o] : 0;
        __syncthreads();
        sh[t] += tmp;
        __syncthreads();
    }
    if (i < n) g_off[i] = sh[t] - v;        // exclusive within chunk
    if (t == 511) g_bsum[blockIdx.x] = sh[511];
}
__global__ void scan2_kernel(int nchunks, int E, int n) {
    __shared__ int sh[512];
    int t = threadIdx.x;
    int v = (t < nchunks) ? g_bsum[t] : 0;
    sh[t] = v;
    __syncthreads();
#pragma unroll
    for (int o = 1; o < 512; o <<= 1) {
        int tmp = (t >= o) ? sh[t - o] : 0;
        __syncthreads();
        sh[t] += tmp;
        __syncthreads();
    }
    if (t < nchunks) g_bsum[t] = sh[t] - v; // exclusive chunk offsets
    if (t == 0) g_off[n] = E;
}
__global__ void scan3_kernel(int n) {
    int i = blockIdx.x * blockDim.x + threadIdx.x;
    if (i < n) {
        int o = g_off[i] + g_bsum[i >> 9];
        g_off[i] = o;
        g_cursor[i] = o;
    }
}
__global__ void scatter_kernel(const void* __restrict__ ei,
                               const float* __restrict__ ec, int E) {
    int is64 = g_idx64;
    for (long long e = blockIdx.x * blockDim.x + threadIdx.x; e < E;
         e += (long long)gridDim.x * blockDim.x) {
        int s = (int)load_index(ei, e, is64);
        int d = (int)load_index(ei, (long long)E + e, is64);
        float w = __ldg(ec + e);
        int pos = atomicAdd(&g_cursor[d], 1);
        g_csr[pos] = make_int2(s, __float_as_int(w));
    }
}

// ---------------- CSR aggregation: agg[v] = sum_j x[src_j] * w_j ---------------
// Warp per node; 8-wide batched gathers for MLP; one 512B store per node.
__global__ __launch_bounds__(256, 4)
void csr_agg_kernel(int n, int sel, const float* __restrict__ xext) {
    int v = blockIdx.x * 8 + (threadIdx.x >> 5);
    if (v >= n) return;
    int lane = threadIdx.x & 31;
    const float* x = pick_x(sel, xext);
    int j = g_off[v], end = g_off[v + 1];
    float4 acc = make_float4(0.f, 0.f, 0.f, 0.f);

    for (; j + 8 <= end; j += 8) {
        int2 e[8];
#pragma unroll
        for (int q = 0; q < 8; q++) e[q] = __ldg(g_csr + j + q);
        float4 vv[8];
#pragma unroll
        for (int q = 0; q < 8; q++)
            vv[q] = *reinterpret_cast<const float4*>(x + (size_t)e[q].x * HD + lane * 4);
#pragma unroll
        for (int q = 0; q < 8; q++) {
            float w = __int_as_float(e[q].y);
            acc.x = fmaf(vv[q].x, w, acc.x);
            acc.y = fmaf(vv[q].y, w, acc.y);
            acc.z = fmaf(vv[q].z, w, acc.z);
            acc.w = fmaf(vv[q].w, w, acc.w);
        }
    }
    for (; j < end; j++) {
        int2 e = __ldg(g_csr + j);
        float w = __int_as_float(e.y);
        float4 vv = *reinterpret_cast<const float4*>(x + (size_t)e.x * HD + lane * 4);
        acc.x = fmaf(vv.x, w, acc.x); acc.y = fmaf(vv.y, w, acc.y);
        acc.z = fmaf(vv.z, w, acc.z); acc.w = fmaf(vv.w, w, acc.w);
    }
    *reinterpret_cast<float4*>(g_agg + (size_t)v * HD + lane * 4) = acc;
}

// ---------------- fallback edge aggregation (atomic path, E > EMAX) ------------
__global__ __launch_bounds__(256, 4)
void edge_agg_kernel(const void* __restrict__ ei,
                     const float* __restrict__ ec,
                     int E, int sel, const float* __restrict__ xext) {
    __shared__ int s_src[EB];
    __shared__ int s_dst[EB];
    __shared__ float s_w[EB];
    int tid = threadIdx.x, wid = tid >> 5, lane = tid & 31;
    int is64 = g_idx64;
    const float* x = pick_x(sel, xext);

    long long base = (long long)blockIdx.x * EB;
    if (base >= E) return;
    int cnt = min(EB, (int)(E - base));
    if (tid < cnt) {
        s_src[tid] = (int)load_index(ei, base + tid, is64);
        s_dst[tid] = (int)load_index(ei, (long long)E + base + tid, is64);
        s_w[tid] = __ldg(ec + base + tid);
    }
    __syncthreads();

    int e = wid;
    if (e < cnt) {
        int s = s_src[e];
        float4 v = *reinterpret_cast<const float4*>(x + (size_t)s * HD + lane * 4);
        while (true) {
            int en = e + 8;
            float4 vn;
            if (en < cnt) {
                int sn = s_src[en];
                vn = *reinterpret_cast<const float4*>(x + (size_t)sn * HD + lane * 4);
            }
            float w = s_w[e];
            int d = s_dst[e];
            float4 o = make_float4(v.x * w, v.y * w, v.z * w, v.w * w);
            red_add_v4(g_agg + (size_t)d * HD + lane * 4, o);
            if (en >= cnt) break;
            v = vn; e = en;
        }
    }
}

// ---------------- tensor-core bf16x3 fused GEMM (persistent, 64-row tiles) -----
// 2 CTAs/SM: one CTA's A-producer overlaps the co-resident CTA's MMA loop.
// MODE 0: A = x_in + agg * nc[row];  C = h1 = A @ W1 + b1; accumulate col stats
// MODE 1: A = relu(h1 * scale[k] + shift[k]); C = x_out = relu(A @ W2 + b2)
#define TM 64                                // tile rows
#define TILE_A_BYTES (TM * BPAD * 2)         // 17408
#define TILE_B_BYTES (HD * BPAD * 2)         // 34816
#define S_AHI 0
#define S_ALO TILE_A_BYTES
#define S_BHI (2 * TILE_A_BYTES)
#define S_BLO (2 * TILE_A_BYTES + TILE_B_BYTES)
#define SMEM_SZ (2 * TILE_A_BYTES + 2 * TILE_B_BYTES)   // 104448

template <int MODE>
__global__ __launch_bounds__(256, 2)
void tgemm_kernel(const float* __restrict__ nc,
                  const float* __restrict__ bias,
                  int n, int sel, int slot,
                  const float* __restrict__ xext) {
    extern __shared__ char smem[];
    uint32_t sb = smem_u32(smem);
    int tid = threadIdx.x, wid = tid >> 5, lane = tid & 31;
    int warp_m = wid & 1;                    // rows warp_m*32
    int warp_n = wid >> 1;                   // cols warp_n*32

    const float* Ain;
    float* Cout;
    if (MODE == 0) { Ain = pick_x(sel, xext); Cout = g_h1; }
    else           { Ain = g_h1;              Cout = sel ? g_xB : g_xA; }

    // ---- copy pre-split W tiles ONCE per CTA (already padded image) ----
    {
        const uint4* wh = (const uint4*)g_Whi[slot];
        const uint4* wl = (const uint4*)g_Wlo[slot];
        uint4* dh = (uint4*)(smem + S_BHI);
        uint4* dl = (uint4*)(smem + S_BLO);
        for (int i = tid; i < TILE_B_BYTES / 16; i += 256) {
            dh[i] = wh[i];
            dl[i] = wl[i];
        }
    }

    // per-lane ldmatrix base offsets
    int lrow = lane & 15;
    int lblk = (lane >> 4) * 16;
    uint32_t aBase = sb + (warp_m * 32 + lrow) * (BPAD * 2) + lblk;
    uint32_t bBase = sb + lrow * (BPAD * 2) + (warp_n * 32) * 2 + lblk;

    int tiles = (n + TM - 1) / TM;
    for (int t = blockIdx.x; t < tiles; t += gridDim.x) {
        int block_row = t * TM;

        // ---- fused A producer: load, fuse, bf16 hi/lo split ----
#pragma unroll 4
        for (int it = 0; it < 8; it++) {
            int f = tid + it * 256;              // 0..2047 float4 slots
            int row = f >> 5;                    // 0..63
            int kk = (f & 31) << 2;              // 0..124
            int grow = block_row + row;
            float4 v = make_float4(0.f, 0.f, 0.f, 0.f);
            if (grow < n) {
                v = *reinterpret_cast<const float4*>(Ain + (size_t)grow * HD + kk);
                if (MODE == 0) {
                    float w = __ldg(nc + grow);
                    float4 u = *reinterpret_cast<const float4*>(g_agg + (size_t)grow * HD + kk);
                    v.x = fmaf(u.x, w, v.x);
                    v.y = fmaf(u.y, w, v.y);
                    v.z = fmaf(u.z, w, v.z);
                    v.w = fmaf(u.w, w, v.w);
                } else {
                    float4 sc = *reinterpret_cast<const float4*>(g_scale + kk);
                    float4 sh = *reinterpret_cast<const float4*>(g_shift + kk);
                    v.x = fmaxf(fmaf(v.x, sc.x, sh.x), 0.f);
                    v.y = fmaxf(fmaf(v.y, sc.y, sh.y), 0.f);
                    v.z = fmaxf(fmaf(v.z, sc.z, sh.z), 0.f);
                    v.w = fmaxf(fmaf(v.w, sc.w, sh.w), 0.f);
                }
            }
            __nv_bfloat16 h0 = __float2bfloat16(v.x);
            __nv_bfloat16 h1 = __float2bfloat16(v.y);
            __nv_bfloat16 h2 = __float2bfloat16(v.z);
            __nv_bfloat16 h3 = __float2bfloat16(v.w);
            __nv_bfloat16 l0 = __float2bfloat16(v.x - __bfloat162float(h0));
            __nv_bfloat16 l1 = __float2bfloat16(v.y - __bfloat162float(h1));
            __nv_bfloat16 l2 = __float2bfloat16(v.z - __bfloat162float(h2));
            __nv_bfloat16 l3 = __float2bfloat16(v.w - __bfloat162float(h3));
            uint2 hp; hp.x = pack_bf(h0, h1); hp.y = pack_bf(h2, h3);
            uint2 lp; lp.x = pack_bf(l0, l1); lp.y = pack_bf(l2, l3);
            int off = row * (BPAD * 2) + kk * 2;     // bytes
            *(uint2*)(smem + S_AHI + off) = hp;
            *(uint2*)(smem + S_ALO + off) = lp;
        }
        __syncthreads();

        // ---- MMA mainloop: 8 k-steps, 3 products, fp32 accumulate ----
        float acc[2][4][4];
#pragma unroll
        for (int mf = 0; mf < 2; mf++)
#pragma unroll
            for (int nf = 0; nf < 4; nf++)
#pragma unroll
                for (int q = 0; q < 4; q++) acc[mf][nf][q] = 0.f;

#pragma unroll
        for (int ks = 0; ks < 8; ks++) {
            uint32_t ah[2][4], al[2][4], bh[4][2], bl[4][2];
#pragma unroll
            for (int mf = 0; mf < 2; mf++) {
                uint32_t addr = aBase + mf * 16 * (BPAD * 2) + ks * 32;
                ldmatrix_x4(ah[mf], addr + S_AHI);
                ldmatrix_x4(al[mf], addr + S_ALO);
            }
#pragma unroll
            for (int nb = 0; nb < 2; nb++) {
                uint32_t addr = bBase + ks * 16 * (BPAD * 2) + nb * 32;
                uint32_t rh[4], rl[4];
                ldmatrix_x4_trans(rh, addr + S_BHI);
                ldmatrix_x4_trans(rl, addr + S_BLO);
                bh[2 * nb][0] = rh[0]; bh[2 * nb][1] = rh[1];
                bh[2 * nb + 1][0] = rh[2]; bh[2 * nb + 1][1] = rh[3];
                bl[2 * nb][0] = rl[0]; bl[2 * nb][1] = rl[1];
                bl[2 * nb + 1][0] = rl[2]; bl[2 * nb + 1][1] = rl[3];
            }
#pragma unroll
            for (int mf = 0; mf < 2; mf++)
#pragma unroll
                for (int nf = 0; nf < 4; nf++) {
                    mma_bf16(acc[mf][nf], ah[mf], bh[nf]);
                    mma_bf16(acc[mf][nf], ah[mf], bl[nf]);
                    mma_bf16(acc[mf][nf], al[mf], bh[nf]);
                }
        }

        // ---- epilogue: bias, (stats | relu), direct fragment stores ----
        int r0 = block_row + warp_m * 32 + (lane >> 2);
#pragma unroll
        for (int nf = 0; nf < 4; nf++) {
            int col = warp_n * 32 + nf * 8 + (lane & 3) * 2;
            float b0 = __ldg(bias + col), b1 = __ldg(bias + col + 1);
            float v[4][2];
#pragma unroll
            for (int mf = 0; mf < 2; mf++) {
                v[mf * 2][0] = acc[mf][nf][0] + b0;
                v[mf * 2][1] = acc[mf][nf][1] + b1;
                v[mf * 2 + 1][0] = acc[mf][nf][2] + b0;
                v[mf * 2 + 1][1] = acc[mf][nf][3] + b1;
            }
            bool val[4];
            val[0] = r0 < n; val[1] = r0 + 8 < n; val[2] = r0 + 16 < n; val[3] = r0 + 24 < n;
            if (MODE == 0) {
                float s0 = 0.f, s1 = 0.f, q0 = 0.f, q1 = 0.f;
#pragma unroll
                for (int p = 0; p < 4; p++) {
                    if (val[p]) {
                        s0 += v[p][0]; q0 += v[p][0] * v[p][0];
                        s1 += v[p][1]; q1 += v[p][1] * v[p][1];
                    }
                }
#pragma unroll
                for (int d = 4; d < 32; d <<= 1) {
                    s0 += __shfl_xor_sync(0xFFFFFFFFu, s0, d);
                    s1 += __shfl_xor_sync(0xFFFFFFFFu, s1, d);
                    q0 += __shfl_xor_sync(0xFFFFFFFFu, q0, d);
                    q1 += __shfl_xor_sync(0xFFFFFFFFu, q1, d);
                }
                if (lane < 4) {
                    int c0 = warp_n * 32 + nf * 8 + lane * 2;
                    atomicAdd(&g_stats[c0], s0);
                    atomicAdd(&g_stats[c0 + 1], s1);
                    atomicAdd(&g_stats[HD + c0], q0);
                    atomicAdd(&g_stats[HD + c0 + 1], q1);
                }
            } else {
#pragma unroll
                for (int p = 0; p < 4; p++) {
                    v[p][0] = fmaxf(v[p][0], 0.f);
                    v[p][1] = fmaxf(v[p][1], 0.f);
                }
            }
#pragma unroll
            for (int p = 0; p < 4; p++) {
                int row = r0 + ((p & 1) ? 8 : 0) + ((p >> 1) ? 16 : 0);
                int pi = (p & 1) + (p >> 1) * 2;
                if (row < n) {
                    float2 o = make_float2(v[pi][0], v[pi][1]);
                    *reinterpret_cast<float2*>(Cout + (size_t)row * HD + col) = o;
                }
            }
        }
        __syncthreads();   // A SMEM reuse barrier before next tile's producer
    }
}

// ---------------- BN parameter computation (self-resetting stats) --------------
__global__ void bn_params_kernel(const float* __restrict__ gamma,
                                 const float* __restrict__ beta, int n) {
    int h = threadIdx.x;
    float invn = 1.f / (float)n;
    float mu = g_stats[h] * invn;
    float var = g_stats[HD + h] * invn - mu * mu;
    float s = gamma[h] * rsqrtf(var + 1e-5f);
    g_scale[h] = s;
    g_shift[h] = beta[h] - mu * s;
    g_stats[h] = 0.f;                 // reset for next layer's tgemm<0>
    g_stats[HD + h] = 0.f;
}

// ---------------- segmented pooling (batch is sorted) ---------------------------
// Warp handles 32 contiguous nodes; register-accumulate runs of equal group id,
// flush with ONE red.v4 per run instead of per node.
__global__ void pool_kernel(const void* __restrict__ batch, int n, int sel) {
    int w = blockIdx.x * (blockDim.x >> 5) + (threadIdx.x >> 5);
    int base = w * 32;
    if (base >= n) return;
    int lane = threadIdx.x & 31;
    int is64 = g_idx64;
    const float* x = sel ? g_xB : g_xA;
    int end = min(base + 32, n);

    float4 acc = make_float4(0.f, 0.f, 0.f, 0.f);
    float cnt = 0.f;
    int cur = (int)load_index(batch, base, is64);
    for (int i = base; i < end; i++) {
        int g = (int)load_index(batch, i, is64);
        if (g != cur) {
            red_add_v4(g_pool + (size_t)cur * HD + lane * 4, acc);
            if (lane == 0) atomicAdd(&g_cnt[cur], cnt);
            acc = make_float4(0.f, 0.f, 0.f, 0.f);
            cnt = 0.f;
            cur = g;
        }
        float4 v = *reinterpret_cast<const float4*>(x + (size_t)i * HD + lane * 4);
        acc.x += v.x; acc.y += v.y; acc.z += v.z; acc.w += v.w;
        cnt += 1.f;
    }
    red_add_v4(g_pool + (size_t)cur * HD + lane * 4, acc);
    if (lane == 0) atomicAdd(&g_cnt[cur], cnt);
}

// ---------------- classifier head ----------------------------------------------
__global__ void head_kernel(const float* __restrict__ Wc,
                            const float* __restrict__ bc,
                            float* __restrict__ out) {
    int g = blockIdx.x;
    int h = threadIdx.x;
    float cnt = g_cnt[g];
    float v = g_pool[g * HD + h] / fmaxf(cnt, 1.f);
    __shared__ float sh[HD];
    for (int c = 0; c < NCLS; c++) {
        sh[h] = v * Wc[h * NCLS + c];
        __syncthreads();
        for (int s = 64; s > 0; s >>= 1) {
            if (h < s) sh[h] += sh[h + s];
            __syncthreads();
        }
        if (h == 0) out[g * NCLS + c] = sh[0] + bc[c];
        __syncthreads();
    }
}

// ---------------- launch ---------------------------------------------------------
extern "C" void kernel_launch(void* const* d_in, const int* in_sizes, int n_in,
                              void* d_out, int out_size) {
    cudaFuncSetAttribute(tgemm_kernel<0>,
                         cudaFuncAttributeMaxDynamicSharedMemorySize, SMEM_SZ);
    cudaFuncSetAttribute(tgemm_kernel<1>,
                         cudaFuncAttributeMaxDynamicSharedMemorySize, SMEM_SZ);

    // Detect input ordering: signature order has edge_index (1.6M elems) at [1];
    // setup_inputs dict order has node_centrality (50K) at [1].
    int ix, iei, ib, inc_, iec, iw1, ib1, ig1, ibe1, iw2, ib2, iwc, ibc;
    ix = 0;
    if (n_in >= 13 && in_sizes[1] > 1000000) {
        iei = 1; ib = 2; inc_ = 3; iec = 4;
        iw1 = 5; ib1 = 6; ig1 = 7; ibe1 = 8;
        iw2 = 9; ib2 = 10; iwc = 11; ibc = 12;
    } else {
        inc_ = 1; iec = 2; iw1 = 3; ib1 = 4; ig1 = 5; ibe1 = 6;
        iw2 = 7; ib2 = 8; iwc = 9; ibc = 10; iei = 11; ib = 12;
    }

    const float* x   = (const float*)d_in[ix];
    const void*  ei  = d_in[iei];
    const void*  bat = d_in[ib];
    const float* nc  = (const float*)d_in[inc_];
    const float* ec  = (const float*)d_in[iec];
    const float* W1  = (const float*)d_in[iw1];
    const float* b1  = (const float*)d_in[ib1];
    const float* g1  = (const float*)d_in[ig1];
    const float* be1 = (const float*)d_in[ibe1];
    const float* W2  = (const float*)d_in[iw2];
    const float* b2  = (const float*)d_in[ib2];
    const float* Wc  = (const float*)d_in[iwc];
    const float* bc  = (const float*)d_in[ibc];
    float* out = (float*)d_out;

    int n = in_sizes[ix] / HD;
    int E = in_sizes[iei] / 2;
    int n4 = n * (HD / 4);
    bool use_csr = (E <= EMAX) && (n <= NMAX);

    // conv_w + idx-detect in one launch (detect result consumed only later)
    conv_w_all_kernel<<<(6 * HD * HD + 255) / 256, 256>>>(W1, W2, ei, E, n);

    int tiles = (n + TM - 1) / TM;
    int gemm_grid = tiles < 296 ? tiles : 296;
    int pool_blocks = (n + 255) / 256;   // 8 warps x 32 nodes per block

    if (use_csr) {
        int nchunks = (n + 511) / 512;
        zero_deg_stats_pool_kernel<<<(n + 256) / 256, 256>>>(n);
        hist_kernel<<<512, 256>>>(ei, E);
        scan1_kernel<<<nchunks, 512>>>(n);
        scan2_kernel<<<1, 512>>>(nchunks, E, n);
        scan3_kernel<<<(n + 255) / 256, 256>>>(n);
        scatter_kernel<<<512, 256>>>(ei, ec, E);
    } else {
        zero_deg_stats_pool_kernel<<<(n + 256) / 256, 256>>>(n);
    }

    int agg_blocks = (n + 7) / 8;
    int edge_blocks = (E + EB - 1) / EB;

    // layer I/O: in x(ext) -> B -> A -> B  (sel<0 means external x)
    int sel_in_tab[3]  = { -1, 1, 0 };
    int sel_out_tab[3] = { 1, 0, 1 };

    for (int l = 0; l < 3; l++) {
        int sel_in = sel_in_tab[l];
        int sel_out = sel_out_tab[l];
        if (use_csr) {
            csr_agg_kernel<<<agg_blocks, 256>>>(n, sel_in, x);
        } else {
            zero_agg_stats_kernel<<<2048, 256>>>(n4);
            edge_agg_kernel<<<edge_blocks, 256>>>(ei, ec, E, sel_in, x);
        }
        tgemm_kernel<0><<<gemm_grid, 256, SMEM_SZ>>>(nc, b1 + l * HD, n, sel_in, l, x);
        bn_params_kernel<<<1, HD>>>(g1 + l * HD, be1 + l * HD, n);
        tgemm_kernel<1><<<gemm_grid, 256, SMEM_SZ>>>(nullptr, b2 + l * HD, n, sel_out, 3 + l, x);
    }

    pool_kernel<<<pool_blocks, 256>>>(bat, n, 1);  // final activations live in g_xB
    head_kernel<<<NG, HD>>>(Wc, bc, out);
}